// round 1
// baseline (speedup 1.0000x reference)
#include <cuda_runtime.h>
#include <math.h>

#define BB   32
#define NN   8
#define PP   6
#define DD   96
#define EE   128
#define HH   8
#define HD   16
#define II   64
#define KK   32
#define LL   768
#define BLR  (BB*LL)      // 24576 rows
#define OUTN 128

// ---------------- scratch (device globals; no runtime allocation) ----------------
__device__ float g_seq [BLR*EE];        // 12.6 MB
__device__ float g_qkv [BLR*3*EE];      // 37.7 MB
__device__ float g_ctx [BLR*EE];        // 12.6 MB
__device__ float g_tmp [BLR*EE];        // 12.6 MB
__device__ float g_hid [BLR*II];        //  6.3 MB
__device__ float g_pn  [DD*KK*PP];
__device__ float g_pos [LL*EE];
__device__ float g_part[LL*BB*OUTN];    // 12.6 MB

// ---------------- prototype normalization ----------------
__global__ void proto_norm_kernel(const float* __restrict__ proto) {
    int i = blockIdx.x * 256 + threadIdx.x;
    if (i >= DD*KK) return;
    float v[PP]; float n2 = 0.f;
#pragma unroll
    for (int p = 0; p < PP; p++) { v[p] = proto[i*PP + p]; n2 += v[p]*v[p]; }
    float nr = fmaxf(sqrtf(n2), 1e-12f);
#pragma unroll
    for (int p = 0; p < PP; p++) g_pn[i*PP + p] = v[p] / nr;
}

// ---------------- positional encoding ----------------
__global__ void pos_kernel() {
    int i = blockIdx.x * 256 + threadIdx.x;   // < LL*EE
    int l = i >> 7, e = i & 127;
    int half = e >> 1;
    float freq = expf(-(float)(2*half) * (logf(10000.0f) / (float)EE));
    float ang = (float)l * freq;
    g_pos[i] = (e & 1) ? cosf(ang) : sinf(ang);
}

// ---------------- embedding: normalize, proto argmax, two tiny matmuls, +pos ----
__global__ __launch_bounds__(256)
void embed_kernel(const float* __restrict__ x,
                  const float* __restrict__ emb_w, const float* __restrict__ emb_b,
                  const float* __restrict__ proj_w, const float* __restrict__ proj_b)
{
    int gwarp = (blockIdx.x * blockDim.x + threadIdx.x) >> 5;
    int lane  = threadIdx.x & 31;
    if (gwarp >= BLR) return;
    int rid = gwarp;
    int d = rid % DD;        // 768 % 96 == 0 so rid%96 = d
    int l = rid % LL;

    float xr[PP]; float n2 = 0.f;
#pragma unroll
    for (int p = 0; p < PP; p++) { xr[p] = x[(size_t)rid*PP + p]; n2 += xr[p]*xr[p]; }
    float nr = fmaxf(sqrtf(n2), 1e-12f);
    float xn[PP];
#pragma unroll
    for (int p = 0; p < PP; p++) xn[p] = xr[p] / nr;

    const float* pn = g_pn + (size_t)d * KK * PP;
    float s = 0.f;
#pragma unroll
    for (int p = 0; p < PP; p++) s += xn[p] * pn[lane*PP + p];

    // argmax over K=32 (one per lane), first-index tie break
    float bv = s; int bi = lane;
#pragma unroll
    for (int o = 16; o > 0; o >>= 1) {
        float ov = __shfl_xor_sync(0xffffffffu, bv, o);
        int   oi = __shfl_xor_sync(0xffffffffu, bi, o);
        if (ov > bv || (ov == bv && oi < bi)) { bv = ov; bi = oi; }
    }
    float sel[PP];
#pragma unroll
    for (int p = 0; p < PP; p++) sel[p] = pn[bi*PP + p];

#pragma unroll
    for (int j = 0; j < 4; j++) {
        int e = lane + (j << 5);
        float v = emb_b[e] + proj_b[e] + g_pos[l*EE + e];
#pragma unroll
        for (int p = 0; p < PP; p++)
            v += xr[p] * emb_w[e*PP + p] + sel[p] * proj_w[e*PP + p];
        g_seq[(size_t)rid*EE + e] = v;
    }
}

// ---------------- generic GEMM: C[M,N] = A[M,K] @ W[N,K]^T + bias, ACT 0=none 1=elu
template <int ACT>
__global__ __launch_bounds__(128)
void gemm64(const float* __restrict__ A, const float* __restrict__ W,
            const float* __restrict__ bias, float* __restrict__ C,
            int M, int N, int Kd)
{
    __shared__ float As[32][65];
    __shared__ float Bs[32][65];
    int tid = threadIdx.x;
    int tx = tid & 7, ty = tid >> 3;      // tx: 8 col-groups of 8, ty: 16 row-groups of 4
    int m0 = blockIdx.y << 6, n0 = blockIdx.x << 6;
    float acc[4][8];
#pragma unroll
    for (int i = 0; i < 4; i++)
#pragma unroll
        for (int j = 0; j < 8; j++) acc[i][j] = 0.f;

    for (int k0 = 0; k0 < Kd; k0 += 32) {
#pragma unroll
        for (int i = 0; i < 16; i++) {
            int idx = tid + (i << 7);
            int r = idx >> 5, c = idx & 31;
            As[c][r] = A[(size_t)(m0 + r) * Kd + k0 + c];
            Bs[c][r] = W[(size_t)(n0 + r) * Kd + k0 + c];
        }
        __syncthreads();
#pragma unroll
        for (int k = 0; k < 32; k++) {
            float a[4], b[8];
#pragma unroll
            for (int i = 0; i < 4; i++) a[i] = As[k][(ty << 2) + i];
#pragma unroll
            for (int j = 0; j < 8; j++) b[j] = Bs[k][(tx << 3) + j];
#pragma unroll
            for (int i = 0; i < 4; i++)
#pragma unroll
                for (int j = 0; j < 8; j++) acc[i][j] = fmaf(a[i], b[j], acc[i][j]);
        }
        __syncthreads();
    }
#pragma unroll
    for (int i = 0; i < 4; i++) {
        int m = m0 + (ty << 2) + i;
#pragma unroll
        for (int j = 0; j < 8; j++) {
            int n = n0 + (tx << 3) + j;
            float v = acc[i][j] + bias[n];
            if (ACT == 1) v = (v > 0.f) ? v : expm1f(v);
            C[(size_t)m * N + n] = v;
        }
    }
}

// ---------------- attention: per (qtile, h, b); K/V in padded smem -------------
// smem: Ks[768][20] + Vs[768][20] + Qs[128][16]  = 131072 bytes
__global__ __launch_bounds__(256)
void attn_kernel(const float* __restrict__ qkv, float* __restrict__ ctx)
{
    extern __shared__ float sm[];
    float* Ks = sm;                 // pad 20: conflict-free float4 row reads
    float* Vs = sm + LL*20;
    float* Qs = sm + 2*LL*20;       // [128][16]
    int qt = blockIdx.x, h = blockIdx.y, b = blockIdx.z;
    int tid = threadIdx.x;
    const float* base = qkv + (size_t)b * LL * (3*EE);

    for (int idx = tid; idx < LL*HD; idx += 256) {
        int m = idx >> 4, j = idx & 15;
        const float* src = base + (size_t)m * (3*EE) + h*HD + j;
        Ks[m*20 + j] = src[EE];
        Vs[m*20 + j] = src[2*EE];
    }
    for (int idx = tid; idx < 128*HD; idx += 256) {
        int r = idx >> 4, j = idx & 15;
        Qs[idx] = base[(size_t)(qt*128 + r) * (3*EE) + h*HD + j];
    }
    __syncthreads();

    int w = tid >> 5, lane = tid & 31;
    const float scale = 0.25f;   // 1/sqrt(16)

    for (int pr = 0; pr < 8; pr++) {
        int lr0 = w*16 + pr*2;                 // local row in Q tile
        int r0  = qt*128 + lr0;                // global row
        const float4* qp0 = (const float4*)(Qs + lr0*16);
        const float4* qp1 = (const float4*)(Qs + (lr0+1)*16);
        float4 qa0=qp0[0], qa1=qp0[1], qa2=qp0[2], qa3=qp0[3];
        float4 qb0=qp1[0], qb1=qp1[1], qb2=qp1[2], qb3=qp1[3];

        float l0[24], l1[24];
        float mx0 = -1e30f, mx1 = -1e30f;
#pragma unroll
        for (int t = 0; t < 24; t++) {
            int m = lane + (t << 5);
            const float4* kp = (const float4*)(Ks + m*20);
            float4 k0 = kp[0], k1 = kp[1], k2 = kp[2], k3 = kp[3];
            float s0 = qa0.x*k0.x + qa0.y*k0.y + qa0.z*k0.z + qa0.w*k0.w
                     + qa1.x*k1.x + qa1.y*k1.y + qa1.z*k1.z + qa1.w*k1.w
                     + qa2.x*k2.x + qa2.y*k2.y + qa2.z*k2.z + qa2.w*k2.w
                     + qa3.x*k3.x + qa3.y*k3.y + qa3.z*k3.z + qa3.w*k3.w;
            float s1 = qb0.x*k0.x + qb0.y*k0.y + qb0.z*k0.z + qb0.w*k0.w
                     + qb1.x*k1.x + qb1.y*k1.y + qb1.z*k1.z + qb1.w*k1.w
                     + qb2.x*k2.x + qb2.y*k2.y + qb2.z*k2.z + qb2.w*k2.w
                     + qb3.x*k3.x + qb3.y*k3.y + qb3.z*k3.z + qb3.w*k3.w;
            s0 *= scale; s1 *= scale;
            l0[t] = s0; l1[t] = s1;
            mx0 = fmaxf(mx0, s0); mx1 = fmaxf(mx1, s1);
        }
#pragma unroll
        for (int o = 16; o > 0; o >>= 1) {
            mx0 = fmaxf(mx0, __shfl_xor_sync(0xffffffffu, mx0, o));
            mx1 = fmaxf(mx1, __shfl_xor_sync(0xffffffffu, mx1, o));
        }
        float sum0 = 0.f, sum1 = 0.f;
#pragma unroll
        for (int t = 0; t < 24; t++) {
            l0[t] = expf(l0[t] - mx0); sum0 += l0[t];
            l1[t] = expf(l1[t] - mx1); sum1 += l1[t];
        }
#pragma unroll
        for (int o = 16; o > 0; o >>= 1) {
            sum0 += __shfl_xor_sync(0xffffffffu, sum0, o);
            sum1 += __shfl_xor_sync(0xffffffffu, sum1, o);
        }
        float acc0[16], acc1[16];
#pragma unroll
        for (int j = 0; j < 16; j++) { acc0[j] = 0.f; acc1[j] = 0.f; }
#pragma unroll
        for (int t = 0; t < 24; t++) {
            int m = lane + (t << 5);
            const float4* vp = (const float4*)(Vs + m*20);
            float4 v0 = vp[0], v1 = vp[1], v2 = vp[2], v3 = vp[3];
            float p0 = l0[t], p1 = l1[t];
            acc0[ 0]+=p0*v0.x; acc0[ 1]+=p0*v0.y; acc0[ 2]+=p0*v0.z; acc0[ 3]+=p0*v0.w;
            acc0[ 4]+=p0*v1.x; acc0[ 5]+=p0*v1.y; acc0[ 6]+=p0*v1.z; acc0[ 7]+=p0*v1.w;
            acc0[ 8]+=p0*v2.x; acc0[ 9]+=p0*v2.y; acc0[10]+=p0*v2.z; acc0[11]+=p0*v2.w;
            acc0[12]+=p0*v3.x; acc0[13]+=p0*v3.y; acc0[14]+=p0*v3.z; acc0[15]+=p0*v3.w;
            acc1[ 0]+=p1*v0.x; acc1[ 1]+=p1*v0.y; acc1[ 2]+=p1*v0.z; acc1[ 3]+=p1*v0.w;
            acc1[ 4]+=p1*v1.x; acc1[ 5]+=p1*v1.y; acc1[ 6]+=p1*v1.z; acc1[ 7]+=p1*v1.w;
            acc1[ 8]+=p1*v2.x; acc1[ 9]+=p1*v2.y; acc1[10]+=p1*v2.z; acc1[11]+=p1*v2.w;
            acc1[12]+=p1*v3.x; acc1[13]+=p1*v3.y; acc1[14]+=p1*v3.z; acc1[15]+=p1*v3.w;
        }
#pragma unroll
        for (int o = 16; o > 0; o >>= 1) {
#pragma unroll
            for (int j = 0; j < 16; j++) {
                acc0[j] += __shfl_xor_sync(0xffffffffu, acc0[j], o);
                acc1[j] += __shfl_xor_sync(0xffffffffu, acc1[j], o);
            }
        }
        float inv0 = 1.f / sum0, inv1 = 1.f / sum1;
        float* op = ctx + (size_t)(b*LL + r0) * EE + h*HD;
#pragma unroll
        for (int j = 0; j < 16; j++) {
            if (lane == j)      op[j]      = acc0[j] * inv0;
            if (lane == 16 + j) op[EE + j] = acc1[j] * inv1;
        }
    }
}

// ---------------- residual + layernorm (warp per row of E=128) ----------------
__global__ __launch_bounds__(256)
void add_ln_kernel(float* __restrict__ seq, const float* __restrict__ delta,
                   const float* __restrict__ gam, const float* __restrict__ bet)
{
    int row  = (blockIdx.x * blockDim.x + threadIdx.x) >> 5;
    int lane = threadIdx.x & 31;
    if (row >= BLR) return;
    size_t off = (size_t)row * EE + lane * 4;
    float4 a = *(const float4*)(seq + off);
    float4 d = *(const float4*)(delta + off);
    float v0 = a.x + d.x, v1 = a.y + d.y, v2 = a.z + d.z, v3 = a.w + d.w;
    float s = v0 + v1 + v2 + v3;
#pragma unroll
    for (int o = 16; o > 0; o >>= 1) s += __shfl_xor_sync(0xffffffffu, s, o);
    float mean = s * (1.0f / EE);
    float c0 = v0 - mean, c1 = v1 - mean, c2 = v2 - mean, c3 = v3 - mean;
    float q = c0*c0 + c1*c1 + c2*c2 + c3*c3;
#pragma unroll
    for (int o = 16; o > 0; o >>= 1) q += __shfl_xor_sync(0xffffffffu, q, o);
    float var = q * (1.0f / EE);
    float r = rsqrtf(var + 1e-5f);
    int e = lane * 4;
    float4 out;
    out.x = c0 * r * gam[e+0] + bet[e+0];
    out.y = c1 * r * gam[e+1] + bet[e+1];
    out.z = c2 * r * gam[e+2] + bet[e+2];
    out.w = c3 * r * gam[e+3] + bet[e+3];
    *(float4*)(seq + off) = out;
}

// ---------------- final projection: per-l partials then deterministic reduce ----
__global__ __launch_bounds__(256)
void final_partial(const float* __restrict__ seq, const float* __restrict__ ow,
                   float* __restrict__ part)
{
    extern __shared__ float smf[];
    float* Ws = smf;                 // [128][129] (o-major, padded)
    float* As = smf + 128*129;       // [32][129]
    int l = blockIdx.x, tid = threadIdx.x;
    for (int idx = tid; idx < OUTN*EE; idx += 256) {
        int o = idx >> 7, e = idx & 127;
        Ws[o*129 + e] = ow[(size_t)o * (LL*EE) + l*EE + e];
    }
    for (int idx = tid; idx < BB*EE; idx += 256) {
        int b = idx >> 7, e = idx & 127;
        As[b*129 + e] = seq[(size_t)b * (LL*EE) + l*EE + e];
    }
    __syncthreads();
    int tx = tid & 15, ty = tid >> 4;   // tx: 16 o-groups of 8, ty: 16 b-pairs
    float acc[2][8];
#pragma unroll
    for (int i = 0; i < 2; i++)
#pragma unroll
        for (int j = 0; j < 8; j++) acc[i][j] = 0.f;
    for (int e = 0; e < EE; e++) {
        float a0 = As[(ty*2 + 0)*129 + e];
        float a1 = As[(ty*2 + 1)*129 + e];
#pragma unroll
        for (int j = 0; j < 8; j++) {
            float w = Ws[(tx*8 + j)*129 + e];
            acc[0][j] += a0 * w;
            acc[1][j] += a1 * w;
        }
    }
#pragma unroll
    for (int i = 0; i < 2; i++)
#pragma unroll
        for (int j = 0; j < 8; j++) {
            int b = ty*2 + i, o = tx*8 + j;
            part[(size_t)l * (BB*OUTN) + b*OUTN + o] = acc[i][j];
        }
}

__global__ void final_reduce(const float* __restrict__ part,
                             const float* __restrict__ out_b, float* __restrict__ out)
{
    int i = blockIdx.x * 256 + threadIdx.x;   // < 4096
    float s = out_b[i & 127];
    for (int l = 0; l < LL; l++) s += part[(size_t)l * (BB*OUTN) + i];
    out[i] = s;
}

// ---------------- host launcher ----------------
extern "C" void kernel_launch(void* const* d_in, const int* in_sizes, int n_in,
                              void* d_out, int out_size)
{
    const float* x          = (const float*)d_in[0];
    const float* prototypes = (const float*)d_in[1];
    const float* emb_w      = (const float*)d_in[2];
    const float* emb_b      = (const float*)d_in[3];
    const float* proj_w     = (const float*)d_in[4];
    const float* proj_b     = (const float*)d_in[5];
    const float* in_proj_w  = (const float*)d_in[6];
    const float* in_proj_b  = (const float*)d_in[7];
    const float* out_proj_w = (const float*)d_in[8];
    const float* out_proj_b = (const float*)d_in[9];
    const float* ln1_s      = (const float*)d_in[10];
    const float* ln1_b      = (const float*)d_in[11];
    const float* ffn_w1     = (const float*)d_in[12];
    const float* ffn_b1     = (const float*)d_in[13];
    const float* ffn_w2     = (const float*)d_in[14];
    const float* ffn_b2     = (const float*)d_in[15];
    const float* ln2_s      = (const float*)d_in[16];
    const float* ln2_b      = (const float*)d_in[17];
    const float* out_w      = (const float*)d_in[18];
    const float* out_b      = (const float*)d_in[19];
    float* out = (float*)d_out;

    float *seq, *qkv, *ctx, *tmp, *hid, *part;
    cudaGetSymbolAddress((void**)&seq,  g_seq);
    cudaGetSymbolAddress((void**)&qkv,  g_qkv);
    cudaGetSymbolAddress((void**)&ctx,  g_ctx);
    cudaGetSymbolAddress((void**)&tmp,  g_tmp);
    cudaGetSymbolAddress((void**)&hid,  g_hid);
    cudaGetSymbolAddress((void**)&part, g_part);

    const int ATTN_SMEM = (2*LL*20 + 128*HD) * 4;        // 131072
    const int FIN_SMEM  = (128*129 + 32*129) * 4;        // 82560
    cudaFuncSetAttribute(attn_kernel,   cudaFuncAttributeMaxDynamicSharedMemorySize, ATTN_SMEM);
    cudaFuncSetAttribute(final_partial, cudaFuncAttributeMaxDynamicSharedMemorySize, FIN_SMEM);

    proto_norm_kernel<<<12, 256>>>(prototypes);
    pos_kernel<<<(LL*EE)/256, 256>>>();
    embed_kernel<<<BLR/8, 256>>>(x, emb_w, emb_b, proj_w, proj_b);

    for (int l = 0; l < 2; l++) {
        // qkv = seq @ in_proj_w[l]^T + b
        gemm64<0><<<dim3(6, BLR/64), 128>>>(seq, in_proj_w + (size_t)l*3*EE*EE,
                                            in_proj_b + l*3*EE, qkv, BLR, 3*EE, EE);
        attn_kernel<<<dim3(6, HH, BB), 256, ATTN_SMEM>>>(qkv, ctx);
        // attn_out = ctx @ out_proj_w[l]^T + b
        gemm64<0><<<dim3(2, BLR/64), 128>>>(ctx, out_proj_w + (size_t)l*EE*EE,
                                            out_proj_b + l*EE, tmp, BLR, EE, EE);
        add_ln_kernel<<<BLR/8, 256>>>(seq, tmp, ln1_s + l*EE, ln1_b + l*EE);
        // h = elu(seq @ w1^T + b1)
        gemm64<1><<<dim3(1, BLR/64), 128>>>(seq, ffn_w1 + (size_t)l*II*EE,
                                            ffn_b1 + l*II, hid, BLR, II, EE);
        // ffn_out = h @ w2^T + b2
        gemm64<0><<<dim3(2, BLR/64), 128>>>(hid, ffn_w2 + (size_t)l*EE*II,
                                            ffn_b2 + l*EE, tmp, BLR, EE, II);
        add_ln_kernel<<<BLR/8, 256>>>(seq, tmp, ln2_s + l*EE, ln2_b + l*EE);
    }

    final_partial<<<LL, 256, FIN_SMEM>>>(seq, out_w, part);
    final_reduce<<<16, 256>>>(part, out_b, out);
}

// round 3
// speedup vs baseline: 2.2037x; 2.2037x over previous
#include <cuda_runtime.h>
#include <math.h>

#define BB   32
#define PP   6
#define DD   96
#define EE   128
#define HH   8
#define HD   16
#define II   64
#define KK   32
#define LL   768
#define BLR  (BB*LL)      // 24576 rows
#define OUTN 128

typedef unsigned long long u64;
__device__ __forceinline__ u64 pack2(float lo, float hi){
    u64 r; asm("mov.b64 %0,{%1,%2};" : "=l"(r) : "f"(lo), "f"(hi)); return r;
}
__device__ __forceinline__ void unpack2(u64 v, float& lo, float& hi){
    asm("mov.b64 {%0,%1},%2;" : "=f"(lo), "=f"(hi) : "l"(v));
}
__device__ __forceinline__ u64 ffma2(u64 a, u64 b, u64 c){
    u64 d; asm("fma.rn.f32x2 %0,%1,%2,%3;" : "=l"(d) : "l"(a), "l"(b), "l"(c)); return d;
}

// ---------------- scratch ----------------
__device__ float g_seq [BLR*EE];
__device__ float g_qkv [BLR*3*EE];
__device__ float g_ctx [BLR*EE];
__device__ float g_tmp [BLR*EE];
__device__ float g_hid [BLR*II];
__device__ float g_pn  [DD*KK*PP];
__device__ float g_pos [LL*EE];
__device__ float g_part[LL*BB*OUTN];

// ---------------- prototype normalization ----------------
__global__ void proto_norm_kernel(const float* __restrict__ proto) {
    int i = blockIdx.x * 256 + threadIdx.x;
    if (i >= DD*KK) return;
    float v[PP]; float n2 = 0.f;
#pragma unroll
    for (int p = 0; p < PP; p++) { v[p] = proto[i*PP + p]; n2 += v[p]*v[p]; }
    float nr = fmaxf(sqrtf(n2), 1e-12f);
#pragma unroll
    for (int p = 0; p < PP; p++) g_pn[i*PP + p] = v[p] / nr;
}

// ---------------- positional encoding ----------------
__global__ void pos_kernel() {
    int i = blockIdx.x * 256 + threadIdx.x;
    int l = i >> 7, e = i & 127;
    int half = e >> 1;
    float freq = expf(-(float)(2*half) * (logf(10000.0f) / (float)EE));
    float ang = (float)l * freq;
    g_pos[i] = (e & 1) ? cosf(ang) : sinf(ang);
}

// ---------------- embedding ----------------
__global__ __launch_bounds__(256)
void embed_kernel(const float* __restrict__ x,
                  const float* __restrict__ emb_w, const float* __restrict__ emb_b,
                  const float* __restrict__ proj_w, const float* __restrict__ proj_b)
{
    int gwarp = (blockIdx.x * blockDim.x + threadIdx.x) >> 5;
    int lane  = threadIdx.x & 31;
    if (gwarp >= BLR) return;
    int rid = gwarp;
    int d = rid % DD;
    int l = rid % LL;

    float xr[PP]; float n2 = 0.f;
#pragma unroll
    for (int p = 0; p < PP; p++) { xr[p] = x[(size_t)rid*PP + p]; n2 += xr[p]*xr[p]; }
    float nr = fmaxf(sqrtf(n2), 1e-12f);
    float xn[PP];
#pragma unroll
    for (int p = 0; p < PP; p++) xn[p] = xr[p] / nr;

    const float* pn = g_pn + (size_t)d * KK * PP;
    float s = 0.f;
#pragma unroll
    for (int p = 0; p < PP; p++) s += xn[p] * pn[lane*PP + p];

    float bv = s; int bi = lane;
#pragma unroll
    for (int o = 16; o > 0; o >>= 1) {
        float ov = __shfl_xor_sync(0xffffffffu, bv, o);
        int   oi = __shfl_xor_sync(0xffffffffu, bi, o);
        if (ov > bv || (ov == bv && oi < bi)) { bv = ov; bi = oi; }
    }
    float sel[PP];
#pragma unroll
    for (int p = 0; p < PP; p++) sel[p] = pn[bi*PP + p];

#pragma unroll
    for (int j = 0; j < 4; j++) {
        int e = lane + (j << 5);
        float v = emb_b[e] + proj_b[e] + g_pos[l*EE + e];
#pragma unroll
        for (int p = 0; p < PP; p++)
            v += xr[p] * emb_w[e*PP + p] + sel[p] * proj_w[e*PP + p];
        g_seq[(size_t)rid*EE + e] = v;
    }
}

// ---------------- GEMM: C[M,N] = A[M,K] @ W[N,K]^T + bias; ACT 1 = ELU --------
// smem stride 68 floats: 16B-aligned (LDS.128-able), 4-way conflict only on the
// transpose stores, conflict-free vector loads. Packed f32x2 accumulators.
template <int ACT>
__global__ __launch_bounds__(128)
void gemm64(const float* __restrict__ A, const float* __restrict__ W,
            const float* __restrict__ bias, float* __restrict__ C,
            int M, int N, int Kd)
{
    __shared__ __align__(16) float As[32*68];
    __shared__ __align__(16) float Bs[32*68];
    int tid = threadIdx.x;
    int tx = tid & 7, ty = tid >> 3;
    int m0 = blockIdx.y << 6, n0 = blockIdx.x << 6;
    u64 acc[4][4];
#pragma unroll
    for (int i = 0; i < 4; i++)
#pragma unroll
        for (int j = 0; j < 4; j++) acc[i][j] = pack2(0.f, 0.f);

    for (int k0 = 0; k0 < Kd; k0 += 32) {
#pragma unroll
        for (int i = 0; i < 16; i++) {
            int idx = tid + (i << 7);
            int r = idx >> 5, c = idx & 31;
            As[c*68 + r] = A[(size_t)(m0 + r) * Kd + k0 + c];
            Bs[c*68 + r] = W[(size_t)(n0 + r) * Kd + k0 + c];
        }
        __syncthreads();
#pragma unroll
        for (int k = 0; k < 32; k++) {
            float4 av = *(const float4*)(As + k*68 + (ty << 2));
            ulonglong2 b01 = *(const ulonglong2*)(Bs + k*68 + (tx << 3));
            ulonglong2 b23 = *(const ulonglong2*)(Bs + k*68 + (tx << 3) + 4);
            u64 a0 = pack2(av.x, av.x), a1 = pack2(av.y, av.y);
            u64 a2 = pack2(av.z, av.z), a3 = pack2(av.w, av.w);
            acc[0][0]=ffma2(a0,b01.x,acc[0][0]); acc[0][1]=ffma2(a0,b01.y,acc[0][1]);
            acc[0][2]=ffma2(a0,b23.x,acc[0][2]); acc[0][3]=ffma2(a0,b23.y,acc[0][3]);
            acc[1][0]=ffma2(a1,b01.x,acc[1][0]); acc[1][1]=ffma2(a1,b01.y,acc[1][1]);
            acc[1][2]=ffma2(a1,b23.x,acc[1][2]); acc[1][3]=ffma2(a1,b23.y,acc[1][3]);
            acc[2][0]=ffma2(a2,b01.x,acc[2][0]); acc[2][1]=ffma2(a2,b01.y,acc[2][1]);
            acc[2][2]=ffma2(a2,b23.x,acc[2][2]); acc[2][3]=ffma2(a2,b23.y,acc[2][3]);
            acc[3][0]=ffma2(a3,b01.x,acc[3][0]); acc[3][1]=ffma2(a3,b01.y,acc[3][1]);
            acc[3][2]=ffma2(a3,b23.x,acc[3][2]); acc[3][3]=ffma2(a3,b23.y,acc[3][3]);
        }
        __syncthreads();
    }
#pragma unroll
    for (int i = 0; i < 4; i++) {
        int m = m0 + (ty << 2) + i;
#pragma unroll
        for (int j = 0; j < 4; j++) {
            int n = n0 + (tx << 3) + j*2;
            float lo, hi; unpack2(acc[i][j], lo, hi);
            lo += bias[n]; hi += bias[n+1];
            if (ACT == 1) {
                lo = (lo > 0.f) ? lo : expm1f(lo);
                hi = (hi > 0.f) ? hi : expm1f(hi);
            }
            float2 o; o.x = lo; o.y = hi;
            *(float2*)(C + (size_t)m * N + n) = o;
        }
    }
}

// ---------------- attention: block=(h,b), 768 threads, 1 Q row each ----------
// K/V in smem (broadcast LDS.128 reads), max-free softmax, packed f32x2 math.
__global__ __launch_bounds__(768)
void attn2_kernel(const float* __restrict__ qkv, float* __restrict__ ctx)
{
    extern __shared__ float sm[];
    float* Ks = sm;                 // [768][16]
    float* Vs = sm + LL*HD;
    int h = blockIdx.x, b = blockIdx.y;
    int tid = threadIdx.x;
    const float* base = qkv + (size_t)b * LL * (3*EE) + h*HD;

    for (int idx = tid; idx < LL*4; idx += 768) {
        int m = idx >> 2, j = (idx & 3) << 2;
        const float* s = base + (size_t)m * (3*EE) + j;
        *(float4*)(Ks + m*HD + j) = *(const float4*)(s + EE);
        *(float4*)(Vs + m*HD + j) = *(const float4*)(s + 2*EE);
    }
    u64 q2[8];
    {
        const float* qp = base + (size_t)tid * (3*EE);
#pragma unroll
        for (int i = 0; i < 4; i++) {
            float4 qv = *(const float4*)(qp + i*4);
            q2[i*2+0] = pack2(qv.x*0.25f, qv.y*0.25f);   // fold 1/sqrt(16)
            q2[i*2+1] = pack2(qv.z*0.25f, qv.w*0.25f);
        }
    }
    __syncthreads();

    u64 acc[8];
#pragma unroll
    for (int i = 0; i < 8; i++) acc[i] = pack2(0.f, 0.f);
    float ssum = 0.f;
    const u64 zero = pack2(0.f, 0.f);

#pragma unroll 2
    for (int m = 0; m < LL; m++) {
        const float* kr = Ks + m*HD;
        ulonglong2 k01 = *(const ulonglong2*)(kr);
        ulonglong2 k23 = *(const ulonglong2*)(kr + 4);
        ulonglong2 k45 = *(const ulonglong2*)(kr + 8);
        ulonglong2 k67 = *(const ulonglong2*)(kr + 12);
        u64 sa = ffma2(q2[0], k01.x, zero);
        u64 sb = ffma2(q2[1], k01.y, zero);
        sa = ffma2(q2[2], k23.x, sa);
        sb = ffma2(q2[3], k23.y, sb);
        sa = ffma2(q2[4], k45.x, sa);
        sb = ffma2(q2[5], k45.y, sb);
        sa = ffma2(q2[6], k67.x, sa);
        sb = ffma2(q2[7], k67.y, sb);
        float alo, ahi, blo, bhi;
        unpack2(sa, alo, ahi); unpack2(sb, blo, bhi);
        float e = __expf((alo + blo) + (ahi + bhi));
        ssum += e;
        u64 ep = pack2(e, e);
        const float* vr = Vs + m*HD;
        ulonglong2 v01 = *(const ulonglong2*)(vr);
        ulonglong2 v23 = *(const ulonglong2*)(vr + 4);
        ulonglong2 v45 = *(const ulonglong2*)(vr + 8);
        ulonglong2 v67 = *(const ulonglong2*)(vr + 12);
        acc[0] = ffma2(ep, v01.x, acc[0]); acc[1] = ffma2(ep, v01.y, acc[1]);
        acc[2] = ffma2(ep, v23.x, acc[2]); acc[3] = ffma2(ep, v23.y, acc[3]);
        acc[4] = ffma2(ep, v45.x, acc[4]); acc[5] = ffma2(ep, v45.y, acc[5]);
        acc[6] = ffma2(ep, v67.x, acc[6]); acc[7] = ffma2(ep, v67.y, acc[7]);
    }
    float inv = 1.0f / ssum;
    float* op = ctx + (size_t)(b*LL + tid) * EE + h*HD;
#pragma unroll
    for (int i = 0; i < 4; i++) {
        float x0, x1, x2, x3;
        unpack2(acc[2*i],   x0, x1);
        unpack2(acc[2*i+1], x2, x3);
        float4 o; o.x = x0*inv; o.y = x1*inv; o.z = x2*inv; o.w = x3*inv;
        *(float4*)(op + i*4) = o;
    }
}

// ---------------- residual + layernorm ----------------
__global__ __launch_bounds__(256)
void add_ln_kernel(float* __restrict__ seq, const float* __restrict__ delta,
                   const float* __restrict__ gam, const float* __restrict__ bet)
{
    int row  = (blockIdx.x * blockDim.x + threadIdx.x) >> 5;
    int lane = threadIdx.x & 31;
    if (row >= BLR) return;
    size_t off = (size_t)row * EE + lane * 4;
    float4 a = *(const float4*)(seq + off);
    float4 d = *(const float4*)(delta + off);
    float v0 = a.x + d.x, v1 = a.y + d.y, v2 = a.z + d.z, v3 = a.w + d.w;
    float s = v0 + v1 + v2 + v3;
#pragma unroll
    for (int o = 16; o > 0; o >>= 1) s += __shfl_xor_sync(0xffffffffu, s, o);
    float mean = s * (1.0f / EE);
    float c0 = v0 - mean, c1 = v1 - mean, c2 = v2 - mean, c3 = v3 - mean;
    float q = c0*c0 + c1*c1 + c2*c2 + c3*c3;
#pragma unroll
    for (int o = 16; o > 0; o >>= 1) q += __shfl_xor_sync(0xffffffffu, q, o);
    float var = q * (1.0f / EE);
    float r = rsqrtf(var + 1e-5f);
    int e = lane * 4;
    float4 out;
    out.x = c0 * r * gam[e+0] + bet[e+0];
    out.y = c1 * r * gam[e+1] + bet[e+1];
    out.z = c2 * r * gam[e+2] + bet[e+2];
    out.w = c3 * r * gam[e+3] + bet[e+3];
    *(float4*)(seq + off) = out;
}

// ---------------- final projection: e-major smem (conflict-free w reads) ------
__global__ __launch_bounds__(256)
void final_partial(const float* __restrict__ seq, const float* __restrict__ ow,
                   float* __restrict__ part)
{
    extern __shared__ float smf[];
    float* Ws  = smf;               // [e][o] stride 136
    float* As2 = smf + 128*136;     // [e][b] stride 34
    int l = blockIdx.x, tid = threadIdx.x;
    for (int idx = tid; idx < OUTN*EE; idx += 256) {
        int o = idx >> 7, e = idx & 127;
        Ws[e*136 + o] = ow[(size_t)o * (LL*EE) + l*EE + e];
    }
    for (int idx = tid; idx < BB*EE; idx += 256) {
        int b = idx >> 7, e = idx & 127;
        As2[e*34 + b] = seq[(size_t)b * (LL*EE) + l*EE + e];
    }
    __syncthreads();
    int tx = tid & 15, ty = tid >> 4;
    float acc[2][8];
#pragma unroll
    for (int i = 0; i < 2; i++)
#pragma unroll
        for (int j = 0; j < 8; j++) acc[i][j] = 0.f;
#pragma unroll 4
    for (int e = 0; e < EE; e++) {
        float a0 = As2[e*34 + ty*2];
        float a1 = As2[e*34 + ty*2 + 1];
        float4 w0 = *(const float4*)(Ws + e*136 + tx*8);
        float4 w1 = *(const float4*)(Ws + e*136 + tx*8 + 4);
        acc[0][0] += a0*w0.x; acc[0][1] += a0*w0.y; acc[0][2] += a0*w0.z; acc[0][3] += a0*w0.w;
        acc[0][4] += a0*w1.x; acc[0][5] += a0*w1.y; acc[0][6] += a0*w1.z; acc[0][7] += a0*w1.w;
        acc[1][0] += a1*w0.x; acc[1][1] += a1*w0.y; acc[1][2] += a1*w0.z; acc[1][3] += a1*w0.w;
        acc[1][4] += a1*w1.x; acc[1][5] += a1*w1.y; acc[1][6] += a1*w1.z; acc[1][7] += a1*w1.w;
    }
#pragma unroll
    for (int i = 0; i < 2; i++)
#pragma unroll
        for (int j = 0; j < 8; j++) {
            int b = ty*2 + i, o = tx*8 + j;
            part[(size_t)l * (BB*OUTN) + b*OUTN + o] = acc[i][j];
        }
}

__global__ void final_reduce(const float* __restrict__ part,
                             const float* __restrict__ out_b, float* __restrict__ out)
{
    int i = blockIdx.x * 256 + threadIdx.x;
    float s0 = 0.f, s1 = 0.f, s2 = 0.f, s3 = 0.f;
    for (int l = 0; l < LL; l += 4) {
        s0 += part[(size_t)(l+0) * (BB*OUTN) + i];
        s1 += part[(size_t)(l+1) * (BB*OUTN) + i];
        s2 += part[(size_t)(l+2) * (BB*OUTN) + i];
        s3 += part[(size_t)(l+3) * (BB*OUTN) + i];
    }
    out[i] = ((s0 + s1) + (s2 + s3)) + out_b[i & 127];
}

// ---------------- host launcher ----------------
extern "C" void kernel_launch(void* const* d_in, const int* in_sizes, int n_in,
                              void* d_out, int out_size)
{
    const float* x          = (const float*)d_in[0];
    const float* prototypes = (const float*)d_in[1];
    const float* emb_w      = (const float*)d_in[2];
    const float* emb_b      = (const float*)d_in[3];
    const float* proj_w     = (const float*)d_in[4];
    const float* proj_b     = (const float*)d_in[5];
    const float* in_proj_w  = (const float*)d_in[6];
    const float* in_proj_b  = (const float*)d_in[7];
    const float* out_proj_w = (const float*)d_in[8];
    const float* out_proj_b = (const float*)d_in[9];
    const float* ln1_s      = (const float*)d_in[10];
    const float* ln1_b      = (const float*)d_in[11];
    const float* ffn_w1     = (const float*)d_in[12];
    const float* ffn_b1     = (const float*)d_in[13];
    const float* ffn_w2     = (const float*)d_in[14];
    const float* ffn_b2     = (const float*)d_in[15];
    const float* ln2_s      = (const float*)d_in[16];
    const float* ln2_b      = (const float*)d_in[17];
    const float* out_w      = (const float*)d_in[18];
    const float* out_b      = (const float*)d_in[19];
    float* out = (float*)d_out;

    float *seq, *qkv, *ctx, *tmp, *hid, *part;
    cudaGetSymbolAddress((void**)&seq,  g_seq);
    cudaGetSymbolAddress((void**)&qkv,  g_qkv);
    cudaGetSymbolAddress((void**)&ctx,  g_ctx);
    cudaGetSymbolAddress((void**)&tmp,  g_tmp);
    cudaGetSymbolAddress((void**)&hid,  g_hid);
    cudaGetSymbolAddress((void**)&part, g_part);

    const int ATTN_SMEM = 2*LL*HD*4;                     // 98304
    const int FIN_SMEM  = (128*136 + 128*34) * 4;        // 87040
    cudaFuncSetAttribute(attn2_kernel,  cudaFuncAttributeMaxDynamicSharedMemorySize, ATTN_SMEM);
    cudaFuncSetAttribute(final_partial, cudaFuncAttributeMaxDynamicSharedMemorySize, FIN_SMEM);

    proto_norm_kernel<<<12, 256>>>(prototypes);
    pos_kernel<<<(LL*EE)/256, 256>>>();
    embed_kernel<<<BLR/8, 256>>>(x, emb_w, emb_b, proj_w, proj_b);

    for (int l = 0; l < 2; l++) {
        gemm64<0><<<dim3(6, BLR/64), 128>>>(seq, in_proj_w + (size_t)l*3*EE*EE,
                                            in_proj_b + l*3*EE, qkv, BLR, 3*EE, EE);
        attn2_kernel<<<dim3(HH, BB), 768, ATTN_SMEM>>>(qkv, ctx);
        gemm64<0><<<dim3(2, BLR/64), 128>>>(ctx, out_proj_w + (size_t)l*EE*EE,
                                            out_proj_b + l*EE, tmp, BLR, EE, EE);
        add_ln_kernel<<<BLR/8, 256>>>(seq, tmp, ln1_s + l*EE, ln1_b + l*EE);
        gemm64<1><<<dim3(1, BLR/64), 128>>>(seq, ffn_w1 + (size_t)l*II*EE,
                                            ffn_b1 + l*II, hid, BLR, II, EE);
        gemm64<0><<<dim3(2, BLR/64), 128>>>(hid, ffn_w2 + (size_t)l*EE*II,
                                            ffn_b2 + l*EE, tmp, BLR, EE, II);
        add_ln_kernel<<<BLR/8, 256>>>(seq, tmp, ln2_s + l*EE, ln2_b + l*EE);
    }

    final_partial<<<LL, 256, FIN_SMEM>>>(seq, out_w, part);
    final_reduce<<<16, 256>>>(part, out_b, out);
}

// round 5
// speedup vs baseline: 2.4827x; 1.1266x over previous
#include <cuda_runtime.h>
#include <cstdint>
#include <math.h>

#define BB   32
#define PP   6
#define DD   96
#define EE   128
#define HH   8
#define HD   16
#define II   64
#define KK   32
#define LL   768
#define BLR  (BB*LL)      // 24576 rows
#define OUTN 128

typedef unsigned long long u64;
__device__ __forceinline__ u64 pack2(float lo, float hi){
    u64 r; asm("mov.b64 %0,{%1,%2};" : "=l"(r) : "f"(lo), "f"(hi)); return r;
}
__device__ __forceinline__ void unpack2(u64 v, float& lo, float& hi){
    asm("mov.b64 {%0,%1},%2;" : "=f"(lo), "=f"(hi) : "l"(v));
}
__device__ __forceinline__ u64 ffma2(u64 a, u64 b, u64 c){
    u64 d; asm("fma.rn.f32x2 %0,%1,%2,%3;" : "=l"(d) : "l"(a), "l"(b), "l"(c)); return d;
}

// ---------------- scratch ----------------
__device__ float g_seq [BLR*EE];
__device__ float g_qkv [BLR*3*EE];
__device__ float g_ctx [BLR*EE];
__device__ float g_hid [BLR*II];
__device__ float g_pn  [DD*KK*PP];
__device__ float g_pos [LL*EE];
__device__ float g_part[LL*BB*OUTN];

// ---------------- prototype normalization ----------------
__global__ void proto_norm_kernel(const float* __restrict__ proto) {
    int i = blockIdx.x * 256 + threadIdx.x;
    if (i >= DD*KK) return;
    float v[PP]; float n2 = 0.f;
#pragma unroll
    for (int p = 0; p < PP; p++) { v[p] = proto[i*PP + p]; n2 += v[p]*v[p]; }
    float nr = fmaxf(sqrtf(n2), 1e-12f);
#pragma unroll
    for (int p = 0; p < PP; p++) g_pn[i*PP + p] = v[p] / nr;
}

// ---------------- positional encoding ----------------
__global__ void pos_kernel() {
    int i = blockIdx.x * 256 + threadIdx.x;
    int l = i >> 7, e = i & 127;
    int half = e >> 1;
    float freq = expf(-(float)(2*half) * (logf(10000.0f) / (float)EE));
    float ang = (float)l * freq;
    g_pos[i] = (e & 1) ? cosf(ang) : sinf(ang);
}

// ---------------- embedding ----------------
__global__ __launch_bounds__(256)
void embed_kernel(const float* __restrict__ x,
                  const float* __restrict__ emb_w, const float* __restrict__ emb_b,
                  const float* __restrict__ proj_w, const float* __restrict__ proj_b)
{
    int gwarp = (blockIdx.x * blockDim.x + threadIdx.x) >> 5;
    int lane  = threadIdx.x & 31;
    if (gwarp >= BLR) return;
    int rid = gwarp;
    int d = rid % DD;
    int l = rid % LL;

    float xr[PP]; float n2 = 0.f;
#pragma unroll
    for (int p = 0; p < PP; p++) { xr[p] = x[(size_t)rid*PP + p]; n2 += xr[p]*xr[p]; }
    float nr = fmaxf(sqrtf(n2), 1e-12f);
    float xn[PP];
#pragma unroll
    for (int p = 0; p < PP; p++) xn[p] = xr[p] / nr;

    const float* pn = g_pn + (size_t)d * KK * PP;
    float s = 0.f;
#pragma unroll
    for (int p = 0; p < PP; p++) s += xn[p] * pn[lane*PP + p];

    float bv = s; int bi = lane;
#pragma unroll
    for (int o = 16; o > 0; o >>= 1) {
        float ov = __shfl_xor_sync(0xffffffffu, bv, o);
        int   oi = __shfl_xor_sync(0xffffffffu, bi, o);
        if (ov > bv || (ov == bv && oi < bi)) { bv = ov; bi = oi; }
    }
    float sel[PP];
#pragma unroll
    for (int p = 0; p < PP; p++) sel[p] = pn[bi*PP + p];

#pragma unroll
    for (int j = 0; j < 4; j++) {
        int e = lane + (j << 5);
        float v = emb_b[e] + proj_b[e] + g_pos[l*EE + e];
#pragma unroll
        for (int p = 0; p < PP; p++)
            v += xr[p] * emb_w[e*PP + p] + sel[p] * proj_w[e*PP + p];
        g_seq[(size_t)rid*EE + e] = v;
    }
}

// ================ SGEMM: C[M,N] = A[M,Kd] @ W[N,Kd]^T + bias ==================
// 256 threads, tile 128 x NT. k-major smem (conflict-free fill, LDS.128 reads).
// ACT=1: ELU. FLN=1: fused residual + layernorm (requires NT==128, N==128;
// C holds the residual stream and is updated in place).
template <int NT, int ACT, int FLN>
__global__ __launch_bounds__(256, 2)
void sgemm(const float* __restrict__ A, const float* __restrict__ W,
           const float* __restrict__ bias, float* __restrict__ C,
           const float* __restrict__ gam, const float* __restrict__ bet,
           int N, int Kd)
{
    constexpr int TX = NT/8;          // threads along n (16 or 8)
    constexpr int TM = TX/2;          // rows per thread (8 or 4)
    constexpr int SA = 132;
    constexpr int SB = NT + 4;
    __shared__ float As[32*SA];
    __shared__ float Bs[32*SB];
    int tid = threadIdx.x;
    int tx = tid % TX, ty = tid / TX;
    int m0 = blockIdx.y << 7, n0 = blockIdx.x * NT;

    u64 acc[TM][4];
#pragma unroll
    for (int i = 0; i < TM; i++)
#pragma unroll
        for (int j = 0; j < 4; j++) acc[i][j] = pack2(0.f, 0.f);

    for (int k0 = 0; k0 < Kd; k0 += 32) {
#pragma unroll
        for (int i = 0; i < 4; i++) {               // A: 1024 float4
            int idx = tid + (i << 8);
            int m = idx >> 3, g = idx & 7;
            float4 v = *(const float4*)(A + (size_t)(m0 + m) * Kd + k0 + g*4);
            As[(g*4+0)*SA + m] = v.x;
            As[(g*4+1)*SA + m] = v.y;
            As[(g*4+2)*SA + m] = v.z;
            As[(g*4+3)*SA + m] = v.w;
        }
#pragma unroll
        for (int i = 0; i < NT*8/256; i++) {        // B: NT*8 float4
            int idx = tid + (i << 8);
            int n = idx >> 3, g = idx & 7;
            float4 v = *(const float4*)(W + (size_t)(n0 + n) * Kd + k0 + g*4);
            Bs[(g*4+0)*SB + n] = v.x;
            Bs[(g*4+1)*SB + n] = v.y;
            Bs[(g*4+2)*SB + n] = v.z;
            Bs[(g*4+3)*SB + n] = v.w;
        }
        __syncthreads();
#pragma unroll
        for (int k = 0; k < 32; k++) {
            ulonglong2 b01 = *(const ulonglong2*)(Bs + k*SB + tx*8);
            ulonglong2 b23 = *(const ulonglong2*)(Bs + k*SB + tx*8 + 4);
            const float* ap = As + k*SA + ty*TM;
#pragma unroll
            for (int i = 0; i < TM; i += 4) {
                float4 av = *(const float4*)(ap + i);
                u64 a0 = pack2(av.x, av.x), a1 = pack2(av.y, av.y);
                u64 a2 = pack2(av.z, av.z), a3 = pack2(av.w, av.w);
                acc[i+0][0]=ffma2(a0,b01.x,acc[i+0][0]); acc[i+0][1]=ffma2(a0,b01.y,acc[i+0][1]);
                acc[i+0][2]=ffma2(a0,b23.x,acc[i+0][2]); acc[i+0][3]=ffma2(a0,b23.y,acc[i+0][3]);
                acc[i+1][0]=ffma2(a1,b01.x,acc[i+1][0]); acc[i+1][1]=ffma2(a1,b01.y,acc[i+1][1]);
                acc[i+1][2]=ffma2(a1,b23.x,acc[i+1][2]); acc[i+1][3]=ffma2(a1,b23.y,acc[i+1][3]);
                acc[i+2][0]=ffma2(a2,b01.x,acc[i+2][0]); acc[i+2][1]=ffma2(a2,b01.y,acc[i+2][1]);
                acc[i+2][2]=ffma2(a2,b23.x,acc[i+2][2]); acc[i+2][3]=ffma2(a2,b23.y,acc[i+2][3]);
                acc[i+3][0]=ffma2(a3,b01.x,acc[i+3][0]); acc[i+3][1]=ffma2(a3,b01.y,acc[i+3][1]);
                acc[i+3][2]=ffma2(a3,b23.x,acc[i+3][2]); acc[i+3][3]=ffma2(a3,b23.y,acc[i+3][3]);
            }
        }
        __syncthreads();
    }

    float4 bv0 = *(const float4*)(bias + n0 + tx*8);
    float4 bv1 = *(const float4*)(bias + n0 + tx*8 + 4);
    float4 gv0, gv1, be0, be1;
    if (FLN) {
        gv0 = *(const float4*)(gam + tx*8);   gv1 = *(const float4*)(gam + tx*8 + 4);
        be0 = *(const float4*)(bet + tx*8);   be1 = *(const float4*)(bet + tx*8 + 4);
    }

#pragma unroll
    for (int i = 0; i < TM; i++) {
        int m = m0 + ty*TM + i;
        float v[8];
        unpack2(acc[i][0], v[0], v[1]);
        unpack2(acc[i][1], v[2], v[3]);
        unpack2(acc[i][2], v[4], v[5]);
        unpack2(acc[i][3], v[6], v[7]);
        v[0]+=bv0.x; v[1]+=bv0.y; v[2]+=bv0.z; v[3]+=bv0.w;
        v[4]+=bv1.x; v[5]+=bv1.y; v[6]+=bv1.z; v[7]+=bv1.w;
        if (ACT) {
#pragma unroll
            for (int j = 0; j < 8; j++) v[j] = (v[j] > 0.f) ? v[j] : expm1f(v[j]);
        }
        float* crow = C + (size_t)m * N + n0 + tx*8;
        if (!FLN) {
            float4 o0; o0.x=v[0]; o0.y=v[1]; o0.z=v[2]; o0.w=v[3];
            float4 o1; o1.x=v[4]; o1.y=v[5]; o1.z=v[6]; o1.w=v[7];
            *(float4*)(crow)     = o0;
            *(float4*)(crow + 4) = o1;
        } else {
            // residual add + layernorm over the full 128-wide row
            float4 s0 = *(const float4*)(crow);
            float4 s1 = *(const float4*)(crow + 4);
            v[0]+=s0.x; v[1]+=s0.y; v[2]+=s0.z; v[3]+=s0.w;
            v[4]+=s1.x; v[5]+=s1.y; v[6]+=s1.z; v[7]+=s1.w;
            float sum = ((v[0]+v[1])+(v[2]+v[3])) + ((v[4]+v[5])+(v[6]+v[7]));
#pragma unroll
            for (int o = 8; o > 0; o >>= 1) sum += __shfl_xor_sync(0xffffffffu, sum, o);
            float mean = sum * (1.0f/128.0f);
            float q = 0.f;
#pragma unroll
            for (int j = 0; j < 8; j++) { v[j] -= mean; q += v[j]*v[j]; }
#pragma unroll
            for (int o = 8; o > 0; o >>= 1) q += __shfl_xor_sync(0xffffffffu, q, o);
            float rstd = rsqrtf(q * (1.0f/128.0f) + 1e-5f);
            float4 o0, o1;
            o0.x = v[0]*rstd*gv0.x + be0.x;  o0.y = v[1]*rstd*gv0.y + be0.y;
            o0.z = v[2]*rstd*gv0.z + be0.z;  o0.w = v[3]*rstd*gv0.w + be0.w;
            o1.x = v[4]*rstd*gv1.x + be1.x;  o1.y = v[5]*rstd*gv1.y + be1.y;
            o1.z = v[6]*rstd*gv1.z + be1.z;  o1.w = v[7]*rstd*gv1.w + be1.w;
            *(float4*)(crow)     = o0;
            *(float4*)(crow + 4) = o1;
        }
    }
}

// ---------------- attention: block=(h,b), 768 threads, 1 Q row each ----------
__global__ __launch_bounds__(768)
void attn2_kernel(const float* __restrict__ qkv, float* __restrict__ ctx)
{
    extern __shared__ float sm[];
    float* Ks = sm;                 // [768][16]
    float* Vs = sm + LL*HD;
    int h = blockIdx.x, b = blockIdx.y;
    int tid = threadIdx.x;
    const float* base = qkv + (size_t)b * LL * (3*EE) + h*HD;

    for (int idx = tid; idx < LL*4; idx += 768) {
        int m = idx >> 2, j = (idx & 3) << 2;
        const float* s = base + (size_t)m * (3*EE) + j;
        *(float4*)(Ks + m*HD + j) = *(const float4*)(s + EE);
        *(float4*)(Vs + m*HD + j) = *(const float4*)(s + 2*EE);
    }
    u64 q2[8];
    {
        const float* qp = base + (size_t)tid * (3*EE);
#pragma unroll
        for (int i = 0; i < 4; i++) {
            float4 qv = *(const float4*)(qp + i*4);
            q2[i*2+0] = pack2(qv.x*0.25f, qv.y*0.25f);
            q2[i*2+1] = pack2(qv.z*0.25f, qv.w*0.25f);
        }
    }
    __syncthreads();

    u64 acc[8];
#pragma unroll
    for (int i = 0; i < 8; i++) acc[i] = pack2(0.f, 0.f);
    float ssum = 0.f;
    const u64 zero = pack2(0.f, 0.f);

#pragma unroll 2
    for (int m = 0; m < LL; m++) {
        const float* kr = Ks + m*HD;
        ulonglong2 k01 = *(const ulonglong2*)(kr);
        ulonglong2 k23 = *(const ulonglong2*)(kr + 4);
        ulonglong2 k45 = *(const ulonglong2*)(kr + 8);
        ulonglong2 k67 = *(const ulonglong2*)(kr + 12);
        u64 sa = ffma2(q2[0], k01.x, zero);
        u64 sb = ffma2(q2[1], k01.y, zero);
        sa = ffma2(q2[2], k23.x, sa);
        sb = ffma2(q2[3], k23.y, sb);
        sa = ffma2(q2[4], k45.x, sa);
        sb = ffma2(q2[5], k45.y, sb);
        sa = ffma2(q2[6], k67.x, sa);
        sb = ffma2(q2[7], k67.y, sb);
        float alo, ahi, blo, bhi;
        unpack2(sa, alo, ahi); unpack2(sb, blo, bhi);
        float e = __expf((alo + blo) + (ahi + bhi));
        ssum += e;
        u64 ep = pack2(e, e);
        const float* vr = Vs + m*HD;
        ulonglong2 v01 = *(const ulonglong2*)(vr);
        ulonglong2 v23 = *(const ulonglong2*)(vr + 4);
        ulonglong2 v45 = *(const ulonglong2*)(vr + 8);
        ulonglong2 v67 = *(const ulonglong2*)(vr + 12);
        acc[0] = ffma2(ep, v01.x, acc[0]); acc[1] = ffma2(ep, v01.y, acc[1]);
        acc[2] = ffma2(ep, v23.x, acc[2]); acc[3] = ffma2(ep, v23.y, acc[3]);
        acc[4] = ffma2(ep, v45.x, acc[4]); acc[5] = ffma2(ep, v45.y, acc[5]);
        acc[6] = ffma2(ep, v67.x, acc[6]); acc[7] = ffma2(ep, v67.y, acc[7]);
    }
    float inv = 1.0f / ssum;
    float* op = ctx + (size_t)(b*LL + tid) * EE + h*HD;
#pragma unroll
    for (int i = 0; i < 4; i++) {
        float x0, x1, x2, x3;
        unpack2(acc[2*i],   x0, x1);
        unpack2(acc[2*i+1], x2, x3);
        float4 o; o.x = x0*inv; o.y = x1*inv; o.z = x2*inv; o.w = x3*inv;
        *(float4*)(op + i*4) = o;
    }
}

// ---------------- final projection ----------------
__global__ __launch_bounds__(256)
void final_partial(const float* __restrict__ seq, const float* __restrict__ ow,
                   float* __restrict__ part)
{
    extern __shared__ float smf[];
    float* Ws  = smf;               // [e][o] stride 136
    float* As2 = smf + 128*136;     // [e][b] stride 34
    int l = blockIdx.x, tid = threadIdx.x;
    for (int idx = tid; idx < OUTN*EE; idx += 256) {
        int o = idx >> 7, e = idx & 127;
        Ws[e*136 + o] = ow[(size_t)o * (LL*EE) + l*EE + e];
    }
    for (int idx = tid; idx < BB*EE; idx += 256) {
        int b = idx >> 7, e = idx & 127;
        As2[e*34 + b] = seq[(size_t)b * (LL*EE) + l*EE + e];
    }
    __syncthreads();
    int tx = tid & 15, ty = tid >> 4;
    float acc[2][8];
#pragma unroll
    for (int i = 0; i < 2; i++)
#pragma unroll
        for (int j = 0; j < 8; j++) acc[i][j] = 0.f;
#pragma unroll 4
    for (int e = 0; e < EE; e++) {
        float a0 = As2[e*34 + ty*2];
        float a1 = As2[e*34 + ty*2 + 1];
        float4 w0 = *(const float4*)(Ws + e*136 + tx*8);
        float4 w1 = *(const float4*)(Ws + e*136 + tx*8 + 4);
        acc[0][0] += a0*w0.x; acc[0][1] += a0*w0.y; acc[0][2] += a0*w0.z; acc[0][3] += a0*w0.w;
        acc[0][4] += a0*w1.x; acc[0][5] += a0*w1.y; acc[0][6] += a0*w1.z; acc[0][7] += a0*w1.w;
        acc[1][0] += a1*w0.x; acc[1][1] += a1*w0.y; acc[1][2] += a1*w0.z; acc[1][3] += a1*w0.w;
        acc[1][4] += a1*w1.x; acc[1][5] += a1*w1.y; acc[1][6] += a1*w1.z; acc[1][7] += a1*w1.w;
    }
#pragma unroll
    for (int i = 0; i < 2; i++)
#pragma unroll
        for (int j = 0; j < 8; j++) {
            int b = ty*2 + i, o = tx*8 + j;
            part[(size_t)l * (BB*OUTN) + b*OUTN + o] = acc[i][j];
        }
}

__global__ void final_reduce(const float* __restrict__ part,
                             const float* __restrict__ out_b, float* __restrict__ out)
{
    int i = blockIdx.x * 256 + threadIdx.x;
    float s0 = 0.f, s1 = 0.f, s2 = 0.f, s3 = 0.f;
    for (int l = 0; l < LL; l += 4) {
        s0 += part[(size_t)(l+0) * (BB*OUTN) + i];
        s1 += part[(size_t)(l+1) * (BB*OUTN) + i];
        s2 += part[(size_t)(l+2) * (BB*OUTN) + i];
        s3 += part[(size_t)(l+3) * (BB*OUTN) + i];
    }
    out[i] = ((s0 + s1) + (s2 + s3)) + out_b[i & 127];
}

// ---------------- host launcher ----------------
extern "C" void kernel_launch(void* const* d_in, const int* in_sizes, int n_in,
                              void* d_out, int out_size)
{
    const float* x          = (const float*)d_in[0];
    const float* prototypes = (const float*)d_in[1];
    const float* emb_w      = (const float*)d_in[2];
    const float* emb_b      = (const float*)d_in[3];
    const float* proj_w     = (const float*)d_in[4];
    const float* proj_b     = (const float*)d_in[5];
    const float* in_proj_w  = (const float*)d_in[6];
    const float* in_proj_b  = (const float*)d_in[7];
    const float* out_proj_w = (const float*)d_in[8];
    const float* out_proj_b = (const float*)d_in[9];
    const float* ln1_s      = (const float*)d_in[10];
    const float* ln1_b      = (const float*)d_in[11];
    const float* ffn_w1     = (const float*)d_in[12];
    const float* ffn_b1     = (const float*)d_in[13];
    const float* ffn_w2     = (const float*)d_in[14];
    const float* ffn_b2     = (const float*)d_in[15];
    const float* ln2_s      = (const float*)d_in[16];
    const float* ln2_b      = (const float*)d_in[17];
    const float* out_w      = (const float*)d_in[18];
    const float* out_b      = (const float*)d_in[19];
    float* out = (float*)d_out;

    float *seq, *qkv, *ctx, *hid, *part;
    cudaGetSymbolAddress((void**)&seq,  g_seq);
    cudaGetSymbolAddress((void**)&qkv,  g_qkv);
    cudaGetSymbolAddress((void**)&ctx,  g_ctx);
    cudaGetSymbolAddress((void**)&hid,  g_hid);
    cudaGetSymbolAddress((void**)&part, g_part);

    const int ATTN_SMEM = 2*LL*HD*4;                     // 98304
    const int FIN_SMEM  = (128*136 + 128*34) * 4;        // 87040
    cudaFuncSetAttribute(attn2_kernel,  cudaFuncAttributeMaxDynamicSharedMemorySize, ATTN_SMEM);
    cudaFuncSetAttribute(final_partial, cudaFuncAttributeMaxDynamicSharedMemorySize, FIN_SMEM);

    proto_norm_kernel<<<12, 256>>>(prototypes);
    pos_kernel<<<(LL*EE)/256, 256>>>();
    embed_kernel<<<BLR/8, 256>>>(x, emb_w, emb_b, proj_w, proj_b);

    for (int l = 0; l < 2; l++) {
        // qkv = seq @ in_proj_w[l]^T + b   (M=24576, N=384, K=128)
        sgemm<128,0,0><<<dim3(3, BLR/128), 256>>>(
            seq, in_proj_w + (size_t)l*3*EE*EE, in_proj_b + l*3*EE, qkv,
            nullptr, nullptr, 3*EE, EE);
        attn2_kernel<<<dim3(HH, BB), 768, ATTN_SMEM>>>(qkv, ctx);
        // seq = LN1(seq + ctx @ out_proj_w[l]^T + b)   (fused)
        sgemm<128,0,1><<<dim3(1, BLR/128), 256>>>(
            ctx, out_proj_w + (size_t)l*EE*EE, out_proj_b + l*EE, seq,
            ln1_s + l*EE, ln1_b + l*EE, EE, EE);
        // hid = elu(seq @ w1^T + b1)   (N=64, K=128)
        sgemm<64,1,0><<<dim3(1, BLR/128), 256>>>(
            seq, ffn_w1 + (size_t)l*II*EE, ffn_b1 + l*II, hid,
            nullptr, nullptr, II, EE);
        // seq = LN2(seq + hid @ w2^T + b2)   (fused; K=64)
        sgemm<128,0,1><<<dim3(1, BLR/128), 256>>>(
            hid, ffn_w2 + (size_t)l*EE*II, ffn_b2 + l*EE, seq,
            ln2_s + l*EE, ln2_b + l*EE, EE, II);
    }

    final_partial<<<LL, 256, FIN_SMEM>>>(seq, out_w, part);
    final_reduce<<<16, 256>>>(part, out_b, out);
}

// round 7
// speedup vs baseline: 2.5202x; 1.0151x over previous
#include <cuda_runtime.h>
#include <cstdint>
#include <math.h>

#define BB   32
#define PP   6
#define DD   96
#define EE   128
#define HH   8
#define HD   16
#define II   64
#define KK   32
#define LL   768
#define BLR  (BB*LL)      // 24576 rows
#define OUTN 128
#define NCH  4
#define CHM  (LL/NCH)     // 192
#define ART  (NCH*20)     // 80 floats per (row,h,b) partial record

typedef unsigned long long u64;
__device__ __forceinline__ u64 pack2(float lo, float hi){
    u64 r; asm("mov.b64 %0,{%1,%2};" : "=l"(r) : "f"(lo), "f"(hi)); return r;
}
__device__ __forceinline__ void unpack2(u64 v, float& lo, float& hi){
    asm("mov.b64 {%0,%1},%2;" : "=f"(lo), "=f"(hi) : "l"(v));
}
__device__ __forceinline__ u64 ffma2(u64 a, u64 b, u64 c){
    u64 d; asm("fma.rn.f32x2 %0,%1,%2,%3;" : "=l"(d) : "l"(a), "l"(b), "l"(c)); return d;
}
__device__ __forceinline__ float ex2f(float x){
    float r; asm("ex2.approx.f32 %0, %1;" : "=f"(r) : "f"(x)); return r;
}

// ---------------- scratch ----------------
__device__ float g_seq  [BLR*EE];
__device__ float g_qkv  [BLR*3*EE];
__device__ float g_ctx  [BLR*EE];
__device__ float g_hid  [BLR*II];
__device__ float g_pn   [DD*KK*PP];
__device__ float g_pos  [LL*EE];
__device__ float g_part [LL*BB*OUTN];
__device__ float g_apart[(size_t)BB*HH*LL*ART];   // attention partials (63MB)

// ---------------- prototype normalization ----------------
__global__ void proto_norm_kernel(const float* __restrict__ proto) {
    int i = blockIdx.x * 256 + threadIdx.x;
    if (i >= DD*KK) return;
    float v[PP]; float n2 = 0.f;
#pragma unroll
    for (int p = 0; p < PP; p++) { v[p] = proto[i*PP + p]; n2 += v[p]*v[p]; }
    float nr = fmaxf(sqrtf(n2), 1e-12f);
#pragma unroll
    for (int p = 0; p < PP; p++) g_pn[i*PP + p] = v[p] / nr;
}

// ---------------- positional encoding ----------------
__global__ void pos_kernel() {
    int i = blockIdx.x * 256 + threadIdx.x;
    int l = i >> 7, e = i & 127;
    int half = e >> 1;
    float freq = expf(-(float)(2*half) * (logf(10000.0f) / (float)EE));
    float ang = (float)l * freq;
    g_pos[i] = (e & 1) ? cosf(ang) : sinf(ang);
}

// ---------------- embedding ----------------
__global__ __launch_bounds__(256)
void embed_kernel(const float* __restrict__ x,
                  const float* __restrict__ emb_w, const float* __restrict__ emb_b,
                  const float* __restrict__ proj_w, const float* __restrict__ proj_b)
{
    int gwarp = (blockIdx.x * blockDim.x + threadIdx.x) >> 5;
    int lane  = threadIdx.x & 31;
    if (gwarp >= BLR) return;
    int rid = gwarp;
    int d = rid % DD;
    int l = rid % LL;

    float xr[PP]; float n2 = 0.f;
#pragma unroll
    for (int p = 0; p < PP; p++) { xr[p] = x[(size_t)rid*PP + p]; n2 += xr[p]*xr[p]; }
    float nr = fmaxf(sqrtf(n2), 1e-12f);
    float xn[PP];
#pragma unroll
    for (int p = 0; p < PP; p++) xn[p] = xr[p] / nr;

    const float* pn = g_pn + (size_t)d * KK * PP;
    float s = 0.f;
#pragma unroll
    for (int p = 0; p < PP; p++) s += xn[p] * pn[lane*PP + p];

    float bv = s; int bi = lane;
#pragma unroll
    for (int o = 16; o > 0; o >>= 1) {
        float ov = __shfl_xor_sync(0xffffffffu, bv, o);
        int   oi = __shfl_xor_sync(0xffffffffu, bi, o);
        if (ov > bv || (ov == bv && oi < bi)) { bv = ov; bi = oi; }
    }
    float sel[PP];
#pragma unroll
    for (int p = 0; p < PP; p++) sel[p] = pn[bi*PP + p];

#pragma unroll
    for (int j = 0; j < 4; j++) {
        int e = lane + (j << 5);
        float v = emb_b[e] + proj_b[e] + g_pos[l*EE + e];
#pragma unroll
        for (int p = 0; p < PP; p++)
            v += xr[p] * emb_w[e*PP + p] + sel[p] * proj_w[e*PP + p];
        g_seq[(size_t)rid*EE + e] = v;
    }
}

// ================ SGEMM: C[M,N] = A[M,Kd] @ W[N,Kd]^T + bias ==================
template <int NT, int ACT, int FLN>
__global__ __launch_bounds__(256, 2)
void sgemm(const float* __restrict__ A, const float* __restrict__ W,
           const float* __restrict__ bias, float* __restrict__ C,
           const float* __restrict__ gam, const float* __restrict__ bet,
           int N, int Kd)
{
    constexpr int TX = NT/8;
    constexpr int TM = TX/2;
    constexpr int SA = 132;
    constexpr int SB = NT + 4;
    __shared__ float As[32*SA];
    __shared__ float Bs[32*SB];
    int tid = threadIdx.x;
    int tx = tid % TX, ty = tid / TX;
    int m0 = blockIdx.y << 7, n0 = blockIdx.x * NT;

    u64 acc[TM][4];
#pragma unroll
    for (int i = 0; i < TM; i++)
#pragma unroll
        for (int j = 0; j < 4; j++) acc[i][j] = pack2(0.f, 0.f);

    for (int k0 = 0; k0 < Kd; k0 += 32) {
#pragma unroll
        for (int i = 0; i < 4; i++) {
            int idx = tid + (i << 8);
            int m = idx >> 3, g = idx & 7;
            float4 v = *(const float4*)(A + (size_t)(m0 + m) * Kd + k0 + g*4);
            As[(g*4+0)*SA + m] = v.x;
            As[(g*4+1)*SA + m] = v.y;
            As[(g*4+2)*SA + m] = v.z;
            As[(g*4+3)*SA + m] = v.w;
        }
#pragma unroll
        for (int i = 0; i < NT*8/256; i++) {
            int idx = tid + (i << 8);
            int n = idx >> 3, g = idx & 7;
            float4 v = *(const float4*)(W + (size_t)(n0 + n) * Kd + k0 + g*4);
            Bs[(g*4+0)*SB + n] = v.x;
            Bs[(g*4+1)*SB + n] = v.y;
            Bs[(g*4+2)*SB + n] = v.z;
            Bs[(g*4+3)*SB + n] = v.w;
        }
        __syncthreads();
#pragma unroll
        for (int k = 0; k < 32; k++) {
            ulonglong2 b01 = *(const ulonglong2*)(Bs + k*SB + tx*8);
            ulonglong2 b23 = *(const ulonglong2*)(Bs + k*SB + tx*8 + 4);
            const float* ap = As + k*SA + ty*TM;
#pragma unroll
            for (int i = 0; i < TM; i += 4) {
                float4 av = *(const float4*)(ap + i);
                u64 a0 = pack2(av.x, av.x), a1 = pack2(av.y, av.y);
                u64 a2 = pack2(av.z, av.z), a3 = pack2(av.w, av.w);
                acc[i+0][0]=ffma2(a0,b01.x,acc[i+0][0]); acc[i+0][1]=ffma2(a0,b01.y,acc[i+0][1]);
                acc[i+0][2]=ffma2(a0,b23.x,acc[i+0][2]); acc[i+0][3]=ffma2(a0,b23.y,acc[i+0][3]);
                acc[i+1][0]=ffma2(a1,b01.x,acc[i+1][0]); acc[i+1][1]=ffma2(a1,b01.y,acc[i+1][1]);
                acc[i+1][2]=ffma2(a1,b23.x,acc[i+1][2]); acc[i+1][3]=ffma2(a1,b23.y,acc[i+1][3]);
                acc[i+2][0]=ffma2(a2,b01.x,acc[i+2][0]); acc[i+2][1]=ffma2(a2,b01.y,acc[i+2][1]);
                acc[i+2][2]=ffma2(a2,b23.x,acc[i+2][2]); acc[i+2][3]=ffma2(a2,b23.y,acc[i+2][3]);
                acc[i+3][0]=ffma2(a3,b01.x,acc[i+3][0]); acc[i+3][1]=ffma2(a3,b01.y,acc[i+3][1]);
                acc[i+3][2]=ffma2(a3,b23.x,acc[i+3][2]); acc[i+3][3]=ffma2(a3,b23.y,acc[i+3][3]);
            }
        }
        __syncthreads();
    }

    float4 bv0 = *(const float4*)(bias + n0 + tx*8);
    float4 bv1 = *(const float4*)(bias + n0 + tx*8 + 4);
    float4 gv0, gv1, be0, be1;
    if (FLN) {
        gv0 = *(const float4*)(gam + tx*8);   gv1 = *(const float4*)(gam + tx*8 + 4);
        be0 = *(const float4*)(bet + tx*8);   be1 = *(const float4*)(bet + tx*8 + 4);
    }

#pragma unroll
    for (int i = 0; i < TM; i++) {
        int m = m0 + ty*TM + i;
        float v[8];
        unpack2(acc[i][0], v[0], v[1]);
        unpack2(acc[i][1], v[2], v[3]);
        unpack2(acc[i][2], v[4], v[5]);
        unpack2(acc[i][3], v[6], v[7]);
        v[0]+=bv0.x; v[1]+=bv0.y; v[2]+=bv0.z; v[3]+=bv0.w;
        v[4]+=bv1.x; v[5]+=bv1.y; v[6]+=bv1.z; v[7]+=bv1.w;
        if (ACT) {
#pragma unroll
            for (int j = 0; j < 8; j++) v[j] = (v[j] > 0.f) ? v[j] : expm1f(v[j]);
        }
        float* crow = C + (size_t)m * N + n0 + tx*8;
        if (!FLN) {
            float4 o0; o0.x=v[0]; o0.y=v[1]; o0.z=v[2]; o0.w=v[3];
            float4 o1; o1.x=v[4]; o1.y=v[5]; o1.z=v[6]; o1.w=v[7];
            *(float4*)(crow)     = o0;
            *(float4*)(crow + 4) = o1;
        } else {
            float4 s0 = *(const float4*)(crow);
            float4 s1 = *(const float4*)(crow + 4);
            v[0]+=s0.x; v[1]+=s0.y; v[2]+=s0.z; v[3]+=s0.w;
            v[4]+=s1.x; v[5]+=s1.y; v[6]+=s1.z; v[7]+=s1.w;
            float sum = ((v[0]+v[1])+(v[2]+v[3])) + ((v[4]+v[5])+(v[6]+v[7]));
#pragma unroll
            for (int o = 8; o > 0; o >>= 1) sum += __shfl_xor_sync(0xffffffffu, sum, o);
            float mean = sum * (1.0f/128.0f);
            float q = 0.f;
#pragma unroll
            for (int j = 0; j < 8; j++) { v[j] -= mean; q += v[j]*v[j]; }
#pragma unroll
            for (int o = 8; o > 0; o >>= 1) q += __shfl_xor_sync(0xffffffffu, q, o);
            float rstd = rsqrtf(q * (1.0f/128.0f) + 1e-5f);
            float4 o0, o1;
            o0.x = v[0]*rstd*gv0.x + be0.x;  o0.y = v[1]*rstd*gv0.y + be0.y;
            o0.z = v[2]*rstd*gv0.z + be0.z;  o0.w = v[3]*rstd*gv0.w + be0.w;
            o1.x = v[4]*rstd*gv1.x + be1.x;  o1.y = v[5]*rstd*gv1.y + be1.y;
            o1.z = v[6]*rstd*gv1.z + be1.z;  o1.w = v[7]*rstd*gv1.w + be1.w;
            *(float4*)(crow)     = o0;
            *(float4*)(crow + 4) = o1;
        }
    }
}

// ---------- attention pass 1: block=(h,b,mchunk); 384 thr, 2 Q rows/thread ----
// K/V chunk in smem; unnormalized exp-weighted partial sums + partial ssum out.
__global__ __launch_bounds__(384)
void attn3_kernel(const float* __restrict__ qkv, float* __restrict__ apart)
{
    extern __shared__ float sm[];
    float* Ks = sm;                 // [CHM][16]
    float* Vs = sm + CHM*HD;
    int h = blockIdx.x, b = blockIdx.y, mc = blockIdx.z;
    int tid = threadIdx.x;
    const float* base  = qkv + (size_t)b * LL * (3*EE) + h*HD;
    const float* kbase = base + (size_t)(mc*CHM) * (3*EE);

    for (int idx = tid; idx < CHM*4; idx += 384) {
        int m = idx >> 2, j = (idx & 3) << 2;
        const float* s = kbase + (size_t)m * (3*EE) + j;
        *(float4*)(Ks + m*HD + j) = *(const float4*)(s + EE);
        *(float4*)(Vs + m*HD + j) = *(const float4*)(s + 2*EE);
    }

    const float SC = 0.25f * 1.4426950408889634f;   // scale * log2(e)
    int r0 = tid, r1 = tid + 384;
    u64 qa[8], qb[8];
    {
        const float* qp = base + (size_t)r0 * (3*EE);
#pragma unroll
        for (int i = 0; i < 4; i++) {
            float4 qv = *(const float4*)(qp + i*4);
            qa[i*2+0] = pack2(qv.x*SC, qv.y*SC);
            qa[i*2+1] = pack2(qv.z*SC, qv.w*SC);
        }
        const float* qp2 = base + (size_t)r1 * (3*EE);
#pragma unroll
        for (int i = 0; i < 4; i++) {
            float4 qv = *(const float4*)(qp2 + i*4);
            qb[i*2+0] = pack2(qv.x*SC, qv.y*SC);
            qb[i*2+1] = pack2(qv.z*SC, qv.w*SC);
        }
    }
    __syncthreads();

    u64 acca[8], accb[8];
#pragma unroll
    for (int i = 0; i < 8; i++) { acca[i] = pack2(0.f,0.f); accb[i] = pack2(0.f,0.f); }
    float suma = 0.f, sumb = 0.f;
    const u64 zero = pack2(0.f, 0.f);

    for (int m = 0; m < CHM; m++) {
        const float* kr = Ks + m*HD;
        ulonglong2 k01 = *(const ulonglong2*)(kr);
        ulonglong2 k23 = *(const ulonglong2*)(kr + 4);
        ulonglong2 k45 = *(const ulonglong2*)(kr + 8);
        ulonglong2 k67 = *(const ulonglong2*)(kr + 12);
        // row 0
        u64 t0 = ffma2(qa[0], k01.x, zero);
        u64 t1 = ffma2(qa[1], k01.y, zero);
        t0 = ffma2(qa[2], k23.x, t0);
        t1 = ffma2(qa[3], k23.y, t1);
        t0 = ffma2(qa[4], k45.x, t0);
        t1 = ffma2(qa[5], k45.y, t1);
        t0 = ffma2(qa[6], k67.x, t0);
        t1 = ffma2(qa[7], k67.y, t1);
        // row 1
        u64 u0 = ffma2(qb[0], k01.x, zero);
        u64 u1 = ffma2(qb[1], k01.y, zero);
        u0 = ffma2(qb[2], k23.x, u0);
        u1 = ffma2(qb[3], k23.y, u1);
        u0 = ffma2(qb[4], k45.x, u0);
        u1 = ffma2(qb[5], k45.y, u1);
        u0 = ffma2(qb[6], k67.x, u0);
        u1 = ffma2(qb[7], k67.y, u1);
        float x0,x1,y0,y1;
        unpack2(t0,x0,x1); unpack2(t1,y0,y1);
        float ea = ex2f((x0+y0)+(x1+y1));
        unpack2(u0,x0,x1); unpack2(u1,y0,y1);
        float eb = ex2f((x0+y0)+(x1+y1));
        suma += ea; sumb += eb;
        u64 epa = pack2(ea, ea);
        u64 epb = pack2(eb, eb);
        const float* vr = Vs + m*HD;
        ulonglong2 v01 = *(const ulonglong2*)(vr);
        ulonglong2 v23 = *(const ulonglong2*)(vr + 4);
        ulonglong2 v45 = *(const ulonglong2*)(vr + 8);
        ulonglong2 v67 = *(const ulonglong2*)(vr + 12);
        acca[0]=ffma2(epa,v01.x,acca[0]); acca[1]=ffma2(epa,v01.y,acca[1]);
        acca[2]=ffma2(epa,v23.x,acca[2]); acca[3]=ffma2(epa,v23.y,acca[3]);
        acca[4]=ffma2(epa,v45.x,acca[4]); acca[5]=ffma2(epa,v45.y,acca[5]);
        acca[6]=ffma2(epa,v67.x,acca[6]); acca[7]=ffma2(epa,v67.y,acca[7]);
        accb[0]=ffma2(epb,v01.x,accb[0]); accb[1]=ffma2(epb,v01.y,accb[1]);
        accb[2]=ffma2(epb,v23.x,accb[2]); accb[3]=ffma2(epb,v23.y,accb[3]);
        accb[4]=ffma2(epb,v45.x,accb[4]); accb[5]=ffma2(epb,v45.y,accb[5]);
        accb[6]=ffma2(epb,v67.x,accb[6]); accb[7]=ffma2(epb,v67.y,accb[7]);
    }

    size_t bh = (size_t)(b*HH + h) * LL;
    {
        float* pr = apart + (bh + r0) * ART + mc*20;
#pragma unroll
        for (int i = 0; i < 4; i++) {
            float p0,p1,p2,p3;
            unpack2(acca[2*i],   p0, p1);
            unpack2(acca[2*i+1], p2, p3);
            float4 o; o.x=p0; o.y=p1; o.z=p2; o.w=p3;
            *(float4*)(pr + i*4) = o;
        }
        pr[16] = suma;
        float* pr2 = apart + (bh + r1) * ART + mc*20;
#pragma unroll
        for (int i = 0; i < 4; i++) {
            float p0,p1,p2,p3;
            unpack2(accb[2*i],   p0, p1);
            unpack2(accb[2*i+1], p2, p3);
            float4 o; o.x=p0; o.y=p1; o.z=p2; o.w=p3;
            *(float4*)(pr2 + i*4) = o;
        }
        pr2[16] = sumb;
    }
}

// ---------- attention pass 2: combine NCH partials, normalize, write ctx ------
__global__ __launch_bounds__(256)
void attn_combine_kernel(const float* __restrict__ apart, float* __restrict__ ctx)
{
    int i = blockIdx.x * 256 + threadIdx.x;     // < BB*HH*LL
    int bh = i / LL, r = i % LL;
    int b = bh >> 3, h = bh & 7;
    const float* p = apart + (size_t)i * ART;
    float s = ((p[16] + p[36]) + (p[56] + p[76]));
    float inv = 1.0f / s;
    float* op = ctx + ((size_t)b*LL + r) * EE + h*HD;
#pragma unroll
    for (int j = 0; j < 4; j++) {
        float4 a0 = *(const float4*)(p + j*4);
        float4 a1 = *(const float4*)(p + 20 + j*4);
        float4 a2 = *(const float4*)(p + 40 + j*4);
        float4 a3 = *(const float4*)(p + 60 + j*4);
        float4 o;
        o.x = ((a0.x + a1.x) + (a2.x + a3.x)) * inv;
        o.y = ((a0.y + a1.y) + (a2.y + a3.y)) * inv;
        o.z = ((a0.z + a1.z) + (a2.z + a3.z)) * inv;
        o.w = ((a0.w + a1.w) + (a2.w + a3.w)) * inv;
        *(float4*)(op + j*4) = o;
    }
}

// ---------------- final projection (packed ffma2) ----------------
__global__ __launch_bounds__(256)
void final_partial(const float* __restrict__ seq, const float* __restrict__ ow,
                   float* __restrict__ part)
{
    extern __shared__ float smf[];
    float* Ws  = smf;               // [e][o] stride 136
    float* As2 = smf + 128*136;     // [e][b] stride 34
    int l = blockIdx.x, tid = threadIdx.x;
    for (int idx = tid; idx < OUTN*EE; idx += 256) {
        int o = idx >> 7, e = idx & 127;
        Ws[e*136 + o] = ow[(size_t)o * (LL*EE) + l*EE + e];
    }
    for (int idx = tid; idx < BB*EE; idx += 256) {
        int b = idx >> 7, e = idx & 127;
        As2[e*34 + b] = seq[(size_t)b * (LL*EE) + l*EE + e];
    }
    __syncthreads();
    int tx = tid & 15, ty = tid >> 4;
    u64 acc[2][4];
#pragma unroll
    for (int i = 0; i < 2; i++)
#pragma unroll
        for (int j = 0; j < 4; j++) acc[i][j] = pack2(0.f, 0.f);
#pragma unroll 4
    for (int e = 0; e < EE; e++) {
        u64 a0 = pack2(As2[e*34 + ty*2],     As2[e*34 + ty*2]);
        u64 a1 = pack2(As2[e*34 + ty*2 + 1], As2[e*34 + ty*2 + 1]);
        ulonglong2 w01 = *(const ulonglong2*)(Ws + e*136 + tx*8);
        ulonglong2 w23 = *(const ulonglong2*)(Ws + e*136 + tx*8 + 4);
        acc[0][0]=ffma2(a0,w01.x,acc[0][0]); acc[0][1]=ffma2(a0,w01.y,acc[0][1]);
        acc[0][2]=ffma2(a0,w23.x,acc[0][2]); acc[0][3]=ffma2(a0,w23.y,acc[0][3]);
        acc[1][0]=ffma2(a1,w01.x,acc[1][0]); acc[1][1]=ffma2(a1,w01.y,acc[1][1]);
        acc[1][2]=ffma2(a1,w23.x,acc[1][2]); acc[1][3]=ffma2(a1,w23.y,acc[1][3]);
    }
#pragma unroll
    for (int i = 0; i < 2; i++) {
        int b = ty*2 + i;
        float* dst = part + (size_t)l * (BB*OUTN) + b*OUTN + tx*8;
#pragma unroll
        for (int j = 0; j < 4; j++) {
            float lo, hi; unpack2(acc[i][j], lo, hi);
            float2 o; o.x = lo; o.y = hi;
            *(float2*)(dst + j*2) = o;
        }
    }
}

// ---------------- final reduce: one warp per output ----------------
__global__ __launch_bounds__(256)
void final_reduce2(const float* __restrict__ part,
                   const float* __restrict__ out_b, float* __restrict__ out)
{
    int gw = (blockIdx.x * 256 + threadIdx.x) >> 5;  // 0..4095
    int lane = threadIdx.x & 31;
    float s = 0.f;
#pragma unroll
    for (int t = 0; t < 24; t++)
        s += part[(size_t)(lane + t*32) * (BB*OUTN) + gw];
#pragma unroll
    for (int o = 16; o > 0; o >>= 1) s += __shfl_xor_sync(0xffffffffu, s, o);
    if (lane == 0) out[gw] = s + out_b[gw & 127];
}

// ---------------- host launcher ----------------
extern "C" void kernel_launch(void* const* d_in, const int* in_sizes, int n_in,
                              void* d_out, int out_size)
{
    const float* x          = (const float*)d_in[0];
    const float* prototypes = (const float*)d_in[1];
    const float* emb_w      = (const float*)d_in[2];
    const float* emb_b      = (const float*)d_in[3];
    const float* proj_w     = (const float*)d_in[4];
    const float* proj_b     = (const float*)d_in[5];
    const float* in_proj_w  = (const float*)d_in[6];
    const float* in_proj_b  = (const float*)d_in[7];
    const float* out_proj_w = (const float*)d_in[8];
    const float* out_proj_b = (const float*)d_in[9];
    const float* ln1_s      = (const float*)d_in[10];
    const float* ln1_b      = (const float*)d_in[11];
    const float* ffn_w1     = (const float*)d_in[12];
    const float* ffn_b1     = (const float*)d_in[13];
    const float* ffn_w2     = (const float*)d_in[14];
    const float* ffn_b2     = (const float*)d_in[15];
    const float* ln2_s      = (const float*)d_in[16];
    const float* ln2_b      = (const float*)d_in[17];
    const float* out_w      = (const float*)d_in[18];
    const float* out_b      = (const float*)d_in[19];
    float* out = (float*)d_out;

    float *seq, *qkv, *ctx, *hid, *part, *apart;
    cudaGetSymbolAddress((void**)&seq,   g_seq);
    cudaGetSymbolAddress((void**)&qkv,   g_qkv);
    cudaGetSymbolAddress((void**)&ctx,   g_ctx);
    cudaGetSymbolAddress((void**)&hid,   g_hid);
    cudaGetSymbolAddress((void**)&part,  g_part);
    cudaGetSymbolAddress((void**)&apart, g_apart);

    const int ATTN_SMEM = 2*CHM*HD*4;                    // 24576
    const int FIN_SMEM  = (128*136 + 128*34) * 4;        // 87040
    cudaFuncSetAttribute(attn3_kernel,  cudaFuncAttributeMaxDynamicSharedMemorySize, ATTN_SMEM);
    cudaFuncSetAttribute(final_partial, cudaFuncAttributeMaxDynamicSharedMemorySize, FIN_SMEM);

    proto_norm_kernel<<<12, 256>>>(prototypes);
    pos_kernel<<<(LL*EE)/256, 256>>>();
    embed_kernel<<<BLR/8, 256>>>(x, emb_w, emb_b, proj_w, proj_b);

    for (int l = 0; l < 2; l++) {
        // qkv = seq @ in_proj_w[l]^T + b   (M=24576, N=384, K=128)
        sgemm<128,0,0><<<dim3(3, BLR/128), 256>>>(
            seq, in_proj_w + (size_t)l*3*EE*EE, in_proj_b + l*3*EE, qkv,
            nullptr, nullptr, 3*EE, EE);
        attn3_kernel<<<dim3(HH, BB, NCH), 384, ATTN_SMEM>>>(qkv, apart);
        attn_combine_kernel<<<(BB*HH*LL)/256, 256>>>(apart, ctx);
        // seq = LN1(seq + ctx @ out_proj_w[l]^T + b)   (fused)
        sgemm<128,0,1><<<dim3(1, BLR/128), 256>>>(
            ctx, out_proj_w + (size_t)l*EE*EE, out_proj_b + l*EE, seq,
            ln1_s + l*EE, ln1_b + l*EE, EE, EE);
        // hid = elu(seq @ w1^T + b1)   (N=64, K=128)
        sgemm<64,1,0><<<dim3(1, BLR/128), 256>>>(
            seq, ffn_w1 + (size_t)l*II*EE, ffn_b1 + l*II, hid,
            nullptr, nullptr, II, EE);
        // seq = LN2(seq + hid @ w2^T + b2)   (fused; K=64)
        sgemm<128,0,1><<<dim3(1, BLR/128), 256>>>(
            hid, ffn_w2 + (size_t)l*EE*II, ffn_b2 + l*EE, seq,
            ln2_s + l*EE, ln2_b + l*EE, EE, II);
    }

    final_partial<<<LL, 256, FIN_SMEM>>>(seq, out_w, part);
    final_reduce2<<<(BB*OUTN*32)/256, 256>>>(part, out_b, out);
}

// round 8
// speedup vs baseline: 2.8009x; 1.1114x over previous
#include <cuda_runtime.h>
#include <cstdint>
#include <math.h>

#define BB   32
#define PP   6
#define DD   96
#define EE   128
#define HH   8
#define HD   16
#define II   64
#define KK   32
#define LL   768
#define BLR  (BB*LL)      // 24576 rows
#define OUTN 128
#define NCH  4
#define CHM  (LL/NCH)     // 192
#define ART  (NCH*20)     // 80 floats per (row,h,b) partial record

typedef unsigned long long u64;
__device__ __forceinline__ u64 pack2(float lo, float hi){
    u64 r; asm("mov.b64 %0,{%1,%2};" : "=l"(r) : "f"(lo), "f"(hi)); return r;
}
__device__ __forceinline__ void unpack2(u64 v, float& lo, float& hi){
    asm("mov.b64 {%0,%1},%2;" : "=f"(lo), "=f"(hi) : "l"(v));
}
__device__ __forceinline__ u64 ffma2(u64 a, u64 b, u64 c){
    u64 d; asm("fma.rn.f32x2 %0,%1,%2,%3;" : "=l"(d) : "l"(a), "l"(b), "l"(c)); return d;
}
__device__ __forceinline__ float ex2f(float x){
    float r; asm("ex2.approx.f32 %0, %1;" : "=f"(r) : "f"(x)); return r;
}
__device__ __forceinline__ uint32_t tf32c(float x){
    uint32_t r; asm("cvt.rna.tf32.f32 %0, %1;" : "=r"(r) : "f"(x)); return r;
}
__device__ __forceinline__ void mma8(float* d, uint32_t a0, uint32_t a1,
                                     uint32_t a2, uint32_t a3,
                                     uint32_t b0, uint32_t b1){
    asm volatile("mma.sync.aligned.m16n8k8.row.col.f32.tf32.tf32.f32 "
        "{%0,%1,%2,%3},{%4,%5,%6,%7},{%8,%9},{%0,%1,%2,%3};"
        : "+f"(d[0]), "+f"(d[1]), "+f"(d[2]), "+f"(d[3])
        : "r"(a0), "r"(a1), "r"(a2), "r"(a3), "r"(b0), "r"(b1));
}

// ---------------- scratch ----------------
__device__ float g_seq  [BLR*EE];
__device__ float g_qkv  [BLR*3*EE];
__device__ float g_ctx  [BLR*EE];
__device__ float g_hid  [BLR*II];
__device__ float g_pn   [DD*KK*PP];
__device__ float g_pos  [LL*EE];
__device__ float g_part [LL*BB*OUTN];
__device__ float g_apart[(size_t)BB*HH*LL*ART];

// ---------------- prototype normalization ----------------
__global__ void proto_norm_kernel(const float* __restrict__ proto) {
    int i = blockIdx.x * 256 + threadIdx.x;
    if (i >= DD*KK) return;
    float v[PP]; float n2 = 0.f;
#pragma unroll
    for (int p = 0; p < PP; p++) { v[p] = proto[i*PP + p]; n2 += v[p]*v[p]; }
    float nr = fmaxf(sqrtf(n2), 1e-12f);
#pragma unroll
    for (int p = 0; p < PP; p++) g_pn[i*PP + p] = v[p] / nr;
}

// ---------------- positional encoding ----------------
__global__ void pos_kernel() {
    int i = blockIdx.x * 256 + threadIdx.x;
    int l = i >> 7, e = i & 127;
    int half = e >> 1;
    float freq = expf(-(float)(2*half) * (logf(10000.0f) / (float)EE));
    float ang = (float)l * freq;
    g_pos[i] = (e & 1) ? cosf(ang) : sinf(ang);
}

// ---------------- embedding ----------------
__global__ __launch_bounds__(256)
void embed_kernel(const float* __restrict__ x,
                  const float* __restrict__ emb_w, const float* __restrict__ emb_b,
                  const float* __restrict__ proj_w, const float* __restrict__ proj_b)
{
    int gwarp = (blockIdx.x * blockDim.x + threadIdx.x) >> 5;
    int lane  = threadIdx.x & 31;
    if (gwarp >= BLR) return;
    int rid = gwarp;
    int d = rid % DD;
    int l = rid % LL;

    float xr[PP]; float n2 = 0.f;
#pragma unroll
    for (int p = 0; p < PP; p++) { xr[p] = x[(size_t)rid*PP + p]; n2 += xr[p]*xr[p]; }
    float nr = fmaxf(sqrtf(n2), 1e-12f);
    float xn[PP];
#pragma unroll
    for (int p = 0; p < PP; p++) xn[p] = xr[p] / nr;

    const float* pn = g_pn + (size_t)d * KK * PP;
    float s = 0.f;
#pragma unroll
    for (int p = 0; p < PP; p++) s += xn[p] * pn[lane*PP + p];

    float bv = s; int bi = lane;
#pragma unroll
    for (int o = 16; o > 0; o >>= 1) {
        float ov = __shfl_xor_sync(0xffffffffu, bv, o);
        int   oi = __shfl_xor_sync(0xffffffffu, bi, o);
        if (ov > bv || (ov == bv && oi < bi)) { bv = ov; bi = oi; }
    }
    float sel[PP];
#pragma unroll
    for (int p = 0; p < PP; p++) sel[p] = pn[bi*PP + p];

#pragma unroll
    for (int j = 0; j < 4; j++) {
        int e = lane + (j << 5);
        float v = emb_b[e] + proj_b[e] + g_pos[l*EE + e];
#pragma unroll
        for (int p = 0; p < PP; p++)
            v += xr[p] * emb_w[e*PP + p] + sel[p] * proj_w[e*PP + p];
        g_seq[(size_t)rid*EE + e] = v;
    }
}

// ========== tf32 mma GEMM: C[M,N] = A[M,Kd] @ W[N,Kd]^T + bias ===============
// 256 threads = 8 warps over M (16 rows each). Tile 128 x NT.
// smem holds tf32-converted operands, k-major. ACT=1: ELU. FLN=1: fused
// residual+layernorm (requires NT==N==128; C is the residual stream, updated
// in place).
template <int NT, int ACT, int FLN>
__global__ __launch_bounds__(256, 2)
void mma_gemm(const float* __restrict__ A, const float* __restrict__ W,
              const float* __restrict__ bias, float* __restrict__ C,
              const float* __restrict__ gam, const float* __restrict__ bet,
              int N, int Kd)
{
    constexpr int SA = 132;
    constexpr int SB = NT + 4;
    constexpr int NF = NT/8;
    __shared__ uint32_t As[32*SA];
    __shared__ uint32_t Bs[32*SB];
    int tid = threadIdx.x;
    int w = tid >> 5, lane = tid & 31;
    int m0 = blockIdx.y << 7, n0 = blockIdx.x * NT;
    int mw = w*16;
    int lq = lane >> 2;          // 0..7  (fragment row)
    int lr = lane & 3;           // 0..3  (fragment k / col-pair)

    float acc[NF][4];
#pragma unroll
    for (int j = 0; j < NF; j++)
#pragma unroll
        for (int t = 0; t < 4; t++) acc[j][t] = 0.f;

    for (int k0 = 0; k0 < Kd; k0 += 32) {
#pragma unroll
        for (int i = 0; i < 4; i++) {               // A: 1024 float4
            int idx = tid + (i << 8);
            int m = idx >> 3, g = idx & 7;
            float4 v = *(const float4*)(A + (size_t)(m0 + m) * Kd + k0 + g*4);
            As[(g*4+0)*SA + m] = tf32c(v.x);
            As[(g*4+1)*SA + m] = tf32c(v.y);
            As[(g*4+2)*SA + m] = tf32c(v.z);
            As[(g*4+3)*SA + m] = tf32c(v.w);
        }
#pragma unroll
        for (int i = 0; i < NT*8/256; i++) {        // B: NT*8 float4
            int idx = tid + (i << 8);
            int n = idx >> 3, g = idx & 7;
            float4 v = *(const float4*)(W + (size_t)(n0 + n) * Kd + k0 + g*4);
            Bs[(g*4+0)*SB + n] = tf32c(v.x);
            Bs[(g*4+1)*SB + n] = tf32c(v.y);
            Bs[(g*4+2)*SB + n] = tf32c(v.z);
            Bs[(g*4+3)*SB + n] = tf32c(v.w);
        }
        __syncthreads();
#pragma unroll
        for (int k8 = 0; k8 < 4; k8++) {
            int kk = k8*8;
            uint32_t a0 = As[(kk + lr)*SA + mw + lq];
            uint32_t a1 = As[(kk + lr)*SA + mw + 8 + lq];
            uint32_t a2 = As[(kk + 4 + lr)*SA + mw + lq];
            uint32_t a3 = As[(kk + 4 + lr)*SA + mw + 8 + lq];
#pragma unroll
            for (int j = 0; j < NF; j++) {
                uint32_t b0 = Bs[(kk + lr)*SB + j*8 + lq];
                uint32_t b1 = Bs[(kk + 4 + lr)*SB + j*8 + lq];
                mma8(acc[j], a0, a1, a2, a3, b0, b1);
            }
        }
        __syncthreads();
    }

    int r0 = m0 + mw + lq;       // first row this thread owns (second is r0+8)
    int cb = 2*lr;               // col offset within each 8-wide fragment

    if (!FLN) {
#pragma unroll
        for (int j = 0; j < NF; j++) {
            int n = n0 + j*8 + cb;
            float2 bv = *(const float2*)(bias + n);
            float x0 = acc[j][0] + bv.x, x1 = acc[j][1] + bv.y;
            float x2 = acc[j][2] + bv.x, x3 = acc[j][3] + bv.y;
            if (ACT) {
                x0 = (x0 > 0.f) ? x0 : expm1f(x0);
                x1 = (x1 > 0.f) ? x1 : expm1f(x1);
                x2 = (x2 > 0.f) ? x2 : expm1f(x2);
                x3 = (x3 > 0.f) ? x3 : expm1f(x3);
            }
            float2 o0; o0.x = x0; o0.y = x1;
            float2 o1; o1.x = x2; o1.y = x3;
            *(float2*)(C + (size_t)r0 * N + n)     = o0;
            *(float2*)(C + (size_t)(r0+8) * N + n) = o1;
        }
    } else {
        // N == NT == 128, n0 == 0: full rows live in this warp's quad.
        float s0 = 0.f, s1 = 0.f;
#pragma unroll
        for (int j = 0; j < NF; j++) {
            int n = j*8 + cb;
            float2 bv = *(const float2*)(bias + n);
            float2 e0 = *(const float2*)(C + (size_t)r0*128 + n);
            float2 e1 = *(const float2*)(C + (size_t)(r0+8)*128 + n);
            acc[j][0] += bv.x + e0.x;  acc[j][1] += bv.y + e0.y;
            acc[j][2] += bv.x + e1.x;  acc[j][3] += bv.y + e1.y;
            s0 += acc[j][0] + acc[j][1];
            s1 += acc[j][2] + acc[j][3];
        }
        s0 += __shfl_xor_sync(0xffffffffu, s0, 1);
        s0 += __shfl_xor_sync(0xffffffffu, s0, 2);
        s1 += __shfl_xor_sync(0xffffffffu, s1, 1);
        s1 += __shfl_xor_sync(0xffffffffu, s1, 2);
        float mean0 = s0 * (1.0f/128.0f);
        float mean1 = s1 * (1.0f/128.0f);
        float q0 = 0.f, q1 = 0.f;
#pragma unroll
        for (int j = 0; j < NF; j++) {
            acc[j][0] -= mean0; acc[j][1] -= mean0;
            acc[j][2] -= mean1; acc[j][3] -= mean1;
            q0 += acc[j][0]*acc[j][0] + acc[j][1]*acc[j][1];
            q1 += acc[j][2]*acc[j][2] + acc[j][3]*acc[j][3];
        }
        q0 += __shfl_xor_sync(0xffffffffu, q0, 1);
        q0 += __shfl_xor_sync(0xffffffffu, q0, 2);
        q1 += __shfl_xor_sync(0xffffffffu, q1, 1);
        q1 += __shfl_xor_sync(0xffffffffu, q1, 2);
        float rstd0 = rsqrtf(q0 * (1.0f/128.0f) + 1e-5f);
        float rstd1 = rsqrtf(q1 * (1.0f/128.0f) + 1e-5f);
#pragma unroll
        for (int j = 0; j < NF; j++) {
            int n = j*8 + cb;
            float2 gv = *(const float2*)(gam + n);
            float2 bt = *(const float2*)(bet + n);
            float2 o0, o1;
            o0.x = acc[j][0]*rstd0*gv.x + bt.x;
            o0.y = acc[j][1]*rstd0*gv.y + bt.y;
            o1.x = acc[j][2]*rstd1*gv.x + bt.x;
            o1.y = acc[j][3]*rstd1*gv.y + bt.y;
            *(float2*)(C + (size_t)r0*128 + n)     = o0;
            *(float2*)(C + (size_t)(r0+8)*128 + n) = o1;
        }
    }
}

// ---------- attention pass 1: block=(h,b,mchunk); 384 thr, 2 Q rows/thread ----
__global__ __launch_bounds__(384)
void attn3_kernel(const float* __restrict__ qkv, float* __restrict__ apart)
{
    extern __shared__ float sm[];
    float* Ks = sm;
    float* Vs = sm + CHM*HD;
    int h = blockIdx.x, b = blockIdx.y, mc = blockIdx.z;
    int tid = threadIdx.x;
    const float* base  = qkv + (size_t)b * LL * (3*EE) + h*HD;
    const float* kbase = base + (size_t)(mc*CHM) * (3*EE);

    for (int idx = tid; idx < CHM*4; idx += 384) {
        int m = idx >> 2, j = (idx & 3) << 2;
        const float* s = kbase + (size_t)m * (3*EE) + j;
        *(float4*)(Ks + m*HD + j) = *(const float4*)(s + EE);
        *(float4*)(Vs + m*HD + j) = *(const float4*)(s + 2*EE);
    }

    const float SC = 0.25f * 1.4426950408889634f;
    int r0 = tid, r1 = tid + 384;
    u64 qa[8], qb[8];
    {
        const float* qp = base + (size_t)r0 * (3*EE);
#pragma unroll
        for (int i = 0; i < 4; i++) {
            float4 qv = *(const float4*)(qp + i*4);
            qa[i*2+0] = pack2(qv.x*SC, qv.y*SC);
            qa[i*2+1] = pack2(qv.z*SC, qv.w*SC);
        }
        const float* qp2 = base + (size_t)r1 * (3*EE);
#pragma unroll
        for (int i = 0; i < 4; i++) {
            float4 qv = *(const float4*)(qp2 + i*4);
            qb[i*2+0] = pack2(qv.x*SC, qv.y*SC);
            qb[i*2+1] = pack2(qv.z*SC, qv.w*SC);
        }
    }
    __syncthreads();

    u64 acca[8], accb[8];
#pragma unroll
    for (int i = 0; i < 8; i++) { acca[i] = pack2(0.f,0.f); accb[i] = pack2(0.f,0.f); }
    float suma = 0.f, sumb = 0.f;
    const u64 zero = pack2(0.f, 0.f);

    for (int m = 0; m < CHM; m++) {
        const float* kr = Ks + m*HD;
        ulonglong2 k01 = *(const ulonglong2*)(kr);
        ulonglong2 k23 = *(const ulonglong2*)(kr + 4);
        ulonglong2 k45 = *(const ulonglong2*)(kr + 8);
        ulonglong2 k67 = *(const ulonglong2*)(kr + 12);
        u64 t0 = ffma2(qa[0], k01.x, zero);
        u64 t1 = ffma2(qa[1], k01.y, zero);
        t0 = ffma2(qa[2], k23.x, t0);
        t1 = ffma2(qa[3], k23.y, t1);
        t0 = ffma2(qa[4], k45.x, t0);
        t1 = ffma2(qa[5], k45.y, t1);
        t0 = ffma2(qa[6], k67.x, t0);
        t1 = ffma2(qa[7], k67.y, t1);
        u64 u0 = ffma2(qb[0], k01.x, zero);
        u64 u1 = ffma2(qb[1], k01.y, zero);
        u0 = ffma2(qb[2], k23.x, u0);
        u1 = ffma2(qb[3], k23.y, u1);
        u0 = ffma2(qb[4], k45.x, u0);
        u1 = ffma2(qb[5], k45.y, u1);
        u0 = ffma2(qb[6], k67.x, u0);
        u1 = ffma2(qb[7], k67.y, u1);
        float x0,x1,y0,y1;
        unpack2(t0,x0,x1); unpack2(t1,y0,y1);
        float ea = ex2f((x0+y0)+(x1+y1));
        unpack2(u0,x0,x1); unpack2(u1,y0,y1);
        float eb = ex2f((x0+y0)+(x1+y1));
        suma += ea; sumb += eb;
        u64 epa = pack2(ea, ea);
        u64 epb = pack2(eb, eb);
        const float* vr = Vs + m*HD;
        ulonglong2 v01 = *(const ulonglong2*)(vr);
        ulonglong2 v23 = *(const ulonglong2*)(vr + 4);
        ulonglong2 v45 = *(const ulonglong2*)(vr + 8);
        ulonglong2 v67 = *(const ulonglong2*)(vr + 12);
        acca[0]=ffma2(epa,v01.x,acca[0]); acca[1]=ffma2(epa,v01.y,acca[1]);
        acca[2]=ffma2(epa,v23.x,acca[2]); acca[3]=ffma2(epa,v23.y,acca[3]);
        acca[4]=ffma2(epa,v45.x,acca[4]); acca[5]=ffma2(epa,v45.y,acca[5]);
        acca[6]=ffma2(epa,v67.x,acca[6]); acca[7]=ffma2(epa,v67.y,acca[7]);
        accb[0]=ffma2(epb,v01.x,accb[0]); accb[1]=ffma2(epb,v01.y,accb[1]);
        accb[2]=ffma2(epb,v23.x,accb[2]); accb[3]=ffma2(epb,v23.y,accb[3]);
        accb[4]=ffma2(epb,v45.x,accb[4]); accb[5]=ffma2(epb,v45.y,accb[5]);
        accb[6]=ffma2(epb,v67.x,accb[6]); accb[7]=ffma2(epb,v67.y,accb[7]);
    }

    size_t bh = (size_t)(b*HH + h) * LL;
    {
        float* pr = apart + (bh + r0) * ART + mc*20;
#pragma unroll
        for (int i = 0; i < 4; i++) {
            float p0,p1,p2,p3;
            unpack2(acca[2*i],   p0, p1);
            unpack2(acca[2*i+1], p2, p3);
            float4 o; o.x=p0; o.y=p1; o.z=p2; o.w=p3;
            *(float4*)(pr + i*4) = o;
        }
        pr[16] = suma;
        float* pr2 = apart + (bh + r1) * ART + mc*20;
#pragma unroll
        for (int i = 0; i < 4; i++) {
            float p0,p1,p2,p3;
            unpack2(accb[2*i],   p0, p1);
            unpack2(accb[2*i+1], p2, p3);
            float4 o; o.x=p0; o.y=p1; o.z=p2; o.w=p3;
            *(float4*)(pr2 + i*4) = o;
        }
        pr2[16] = sumb;
    }
}

// ---------- attention pass 2: combine ------------------------------------
__global__ __launch_bounds__(256)
void attn_combine_kernel(const float* __restrict__ apart, float* __restrict__ ctx)
{
    int i = blockIdx.x * 256 + threadIdx.x;
    int bh = i / LL, r = i % LL;
    int b = bh >> 3, h = bh & 7;
    const float* p = apart + (size_t)i * ART;
    float s = ((p[16] + p[36]) + (p[56] + p[76]));
    float inv = 1.0f / s;
    float* op = ctx + ((size_t)b*LL + r) * EE + h*HD;
#pragma unroll
    for (int j = 0; j < 4; j++) {
        float4 a0 = *(const float4*)(p + j*4);
        float4 a1 = *(const float4*)(p + 20 + j*4);
        float4 a2 = *(const float4*)(p + 40 + j*4);
        float4 a3 = *(const float4*)(p + 60 + j*4);
        float4 o;
        o.x = ((a0.x + a1.x) + (a2.x + a3.x)) * inv;
        o.y = ((a0.y + a1.y) + (a2.y + a3.y)) * inv;
        o.z = ((a0.z + a1.z) + (a2.z + a3.z)) * inv;
        o.w = ((a0.w + a1.w) + (a2.w + a3.w)) * inv;
        *(float4*)(op + j*4) = o;
    }
}

// ---------------- final projection (packed ffma2) ----------------
__global__ __launch_bounds__(256)
void final_partial(const float* __restrict__ seq, const float* __restrict__ ow,
                   float* __restrict__ part)
{
    extern __shared__ float smf[];
    float* Ws  = smf;
    float* As2 = smf + 128*136;
    int l = blockIdx.x, tid = threadIdx.x;
    for (int idx = tid; idx < OUTN*EE; idx += 256) {
        int o = idx >> 7, e = idx & 127;
        Ws[e*136 + o] = ow[(size_t)o * (LL*EE) + l*EE + e];
    }
    for (int idx = tid; idx < BB*EE; idx += 256) {
        int b = idx >> 7, e = idx & 127;
        As2[e*34 + b] = seq[(size_t)b * (LL*EE) + l*EE + e];
    }
    __syncthreads();
    int tx = tid & 15, ty = tid >> 4;
    u64 acc[2][4];
#pragma unroll
    for (int i = 0; i < 2; i++)
#pragma unroll
        for (int j = 0; j < 4; j++) acc[i][j] = pack2(0.f, 0.f);
#pragma unroll 4
    for (int e = 0; e < EE; e++) {
        u64 a0 = pack2(As2[e*34 + ty*2],     As2[e*34 + ty*2]);
        u64 a1 = pack2(As2[e*34 + ty*2 + 1], As2[e*34 + ty*2 + 1]);
        ulonglong2 w01 = *(const ulonglong2*)(Ws + e*136 + tx*8);
        ulonglong2 w23 = *(const ulonglong2*)(Ws + e*136 + tx*8 + 4);
        acc[0][0]=ffma2(a0,w01.x,acc[0][0]); acc[0][1]=ffma2(a0,w01.y,acc[0][1]);
        acc[0][2]=ffma2(a0,w23.x,acc[0][2]); acc[0][3]=ffma2(a0,w23.y,acc[0][3]);
        acc[1][0]=ffma2(a1,w01.x,acc[1][0]); acc[1][1]=ffma2(a1,w01.y,acc[1][1]);
        acc[1][2]=ffma2(a1,w23.x,acc[1][2]); acc[1][3]=ffma2(a1,w23.y,acc[1][3]);
    }
#pragma unroll
    for (int i = 0; i < 2; i++) {
        int b = ty*2 + i;
        float* dst = part + (size_t)l * (BB*OUTN) + b*OUTN + tx*8;
#pragma unroll
        for (int j = 0; j < 4; j++) {
            float lo, hi; unpack2(acc[i][j], lo, hi);
            float2 o; o.x = lo; o.y = hi;
            *(float2*)(dst + j*2) = o;
        }
    }
}

// ---------------- final reduce: one warp per output ----------------
__global__ __launch_bounds__(256)
void final_reduce2(const float* __restrict__ part,
                   const float* __restrict__ out_b, float* __restrict__ out)
{
    int gw = (blockIdx.x * 256 + threadIdx.x) >> 5;
    int lane = threadIdx.x & 31;
    float s = 0.f;
#pragma unroll
    for (int t = 0; t < 24; t++)
        s += part[(size_t)(lane + t*32) * (BB*OUTN) + gw];
#pragma unroll
    for (int o = 16; o > 0; o >>= 1) s += __shfl_xor_sync(0xffffffffu, s, o);
    if (lane == 0) out[gw] = s + out_b[gw & 127];
}

// ---------------- host launcher ----------------
extern "C" void kernel_launch(void* const* d_in, const int* in_sizes, int n_in,
                              void* d_out, int out_size)
{
    const float* x          = (const float*)d_in[0];
    const float* prototypes = (const float*)d_in[1];
    const float* emb_w      = (const float*)d_in[2];
    const float* emb_b      = (const float*)d_in[3];
    const float* proj_w     = (const float*)d_in[4];
    const float* proj_b     = (const float*)d_in[5];
    const float* in_proj_w  = (const float*)d_in[6];
    const float* in_proj_b  = (const float*)d_in[7];
    const float* out_proj_w = (const float*)d_in[8];
    const float* out_proj_b = (const float*)d_in[9];
    const float* ln1_s      = (const float*)d_in[10];
    const float* ln1_b      = (const float*)d_in[11];
    const float* ffn_w1     = (const float*)d_in[12];
    const float* ffn_b1     = (const float*)d_in[13];
    const float* ffn_w2     = (const float*)d_in[14];
    const float* ffn_b2     = (const float*)d_in[15];
    const float* ln2_s      = (const float*)d_in[16];
    const float* ln2_b      = (const float*)d_in[17];
    const float* out_w      = (const float*)d_in[18];
    const float* out_b      = (const float*)d_in[19];
    float* out = (float*)d_out;

    float *seq, *qkv, *ctx, *hid, *part, *apart;
    cudaGetSymbolAddress((void**)&seq,   g_seq);
    cudaGetSymbolAddress((void**)&qkv,   g_qkv);
    cudaGetSymbolAddress((void**)&ctx,   g_ctx);
    cudaGetSymbolAddress((void**)&hid,   g_hid);
    cudaGetSymbolAddress((void**)&part,  g_part);
    cudaGetSymbolAddress((void**)&apart, g_apart);

    const int ATTN_SMEM = 2*CHM*HD*4;                    // 24576
    const int FIN_SMEM  = (128*136 + 128*34) * 4;        // 87040
    cudaFuncSetAttribute(attn3_kernel,  cudaFuncAttributeMaxDynamicSharedMemorySize, ATTN_SMEM);
    cudaFuncSetAttribute(final_partial, cudaFuncAttributeMaxDynamicSharedMemorySize, FIN_SMEM);

    proto_norm_kernel<<<12, 256>>>(prototypes);
    pos_kernel<<<(LL*EE)/256, 256>>>();
    embed_kernel<<<BLR/8, 256>>>(x, emb_w, emb_b, proj_w, proj_b);

    for (int l = 0; l < 2; l++) {
        // qkv = seq @ in_proj_w[l]^T + b   (M=24576, N=384, K=128)
        mma_gemm<128,0,0><<<dim3(3, BLR/128), 256>>>(
            seq, in_proj_w + (size_t)l*3*EE*EE, in_proj_b + l*3*EE, qkv,
            nullptr, nullptr, 3*EE, EE);
        attn3_kernel<<<dim3(HH, BB, NCH), 384, ATTN_SMEM>>>(qkv, apart);
        attn_combine_kernel<<<(BB*HH*LL)/256, 256>>>(apart, ctx);
        // seq = LN1(seq + ctx @ out_proj_w[l]^T + b)   (fused)
        mma_gemm<128,0,1><<<dim3(1, BLR/128), 256>>>(
            ctx, out_proj_w + (size_t)l*EE*EE, out_proj_b + l*EE, seq,
            ln1_s + l*EE, ln1_b + l*EE, EE, EE);
        // hid = elu(seq @ w1^T + b1)   (N=64, K=128)
        mma_gemm<64,1,0><<<dim3(1, BLR/128), 256>>>(
            seq, ffn_w1 + (size_t)l*II*EE, ffn_b1 + l*II, hid,
            nullptr, nullptr, II, EE);
        // seq = LN2(seq + hid @ w2^T + b2)   (fused; K=64)
        mma_gemm<128,0,1><<<dim3(1, BLR/128), 256>>>(
            hid, ffn_w2 + (size_t)l*EE*II, ffn_b2 + l*EE, seq,
            ln2_s + l*EE, ln2_b + l*EE, EE, II);
    }

    final_partial<<<LL, 256, FIN_SMEM>>>(seq, out_w, part);
    final_reduce2<<<(BB*OUTN*32)/256, 256>>>(part, out_b, out);
}

// round 12
// speedup vs baseline: 4.6764x; 1.6696x over previous
#include <cuda_runtime.h>
#include <cstdint>
#include <math.h>

#define BB   32
#define PP   6
#define DD   96
#define EE   128
#define HH   8
#define HD   16
#define II   64
#define KK   32
#define LL   768
#define BLR  (BB*LL)      // 24576 rows
#define OUTN 128

typedef unsigned long long u64;
__device__ __forceinline__ u64 pack2(float lo, float hi){
    u64 r; asm("mov.b64 %0,{%1,%2};" : "=l"(r) : "f"(lo), "f"(hi)); return r;
}
__device__ __forceinline__ void unpack2(u64 v, float& lo, float& hi){
    asm("mov.b64 {%0,%1},%2;" : "=f"(lo), "=f"(hi) : "l"(v));
}
__device__ __forceinline__ u64 ffma2(u64 a, u64 b, u64 c){
    u64 d; asm("fma.rn.f32x2 %0,%1,%2,%3;" : "=l"(d) : "l"(a), "l"(b), "l"(c)); return d;
}
__device__ __forceinline__ float ex2f(float x){
    float r; asm("ex2.approx.f32 %0, %1;" : "=f"(r) : "f"(x)); return r;
}
__device__ __forceinline__ uint32_t tf32c(float x){
    uint32_t r; asm("cvt.rna.tf32.f32 %0, %1;" : "=r"(r) : "f"(x)); return r;
}
__device__ __forceinline__ void mma8(float* d, uint32_t a0, uint32_t a1,
                                     uint32_t a2, uint32_t a3,
                                     uint32_t b0, uint32_t b1){
    asm volatile("mma.sync.aligned.m16n8k8.row.col.f32.tf32.tf32.f32 "
        "{%0,%1,%2,%3},{%4,%5,%6,%7},{%8,%9},{%0,%1,%2,%3};"
        : "+f"(d[0]), "+f"(d[1]), "+f"(d[2]), "+f"(d[3])
        : "r"(a0), "r"(a1), "r"(a2), "r"(a3), "r"(b0), "r"(b1));
}

// ---------------- scratch ----------------
__device__ float g_seq  [BLR*EE];
__device__ float g_qkv  [BLR*3*EE];
__device__ float g_ctx  [BLR*EE];
__device__ float g_hid  [BLR*II];
__device__ float g_pn   [DD*KK*PP];
__device__ float g_pos  [LL*EE];
__device__ float g_part [LL*BB*OUTN];

// ---------------- prototype normalization ----------------
__global__ void proto_norm_kernel(const float* __restrict__ proto) {
    int i = blockIdx.x * 256 + threadIdx.x;
    if (i >= DD*KK) return;
    float v[PP]; float n2 = 0.f;
#pragma unroll
    for (int p = 0; p < PP; p++) { v[p] = proto[i*PP + p]; n2 += v[p]*v[p]; }
    float nr = fmaxf(sqrtf(n2), 1e-12f);
#pragma unroll
    for (int p = 0; p < PP; p++) g_pn[i*PP + p] = v[p] / nr;
}

// ---------------- positional encoding ----------------
__global__ void pos_kernel() {
    int i = blockIdx.x * 256 + threadIdx.x;
    int l = i >> 7, e = i & 127;
    int half = e >> 1;
    float freq = expf(-(float)(2*half) * (logf(10000.0f) / (float)EE));
    float ang = (float)l * freq;
    g_pos[i] = (e & 1) ? cosf(ang) : sinf(ang);
}

// ---------------- embedding ----------------
__global__ __launch_bounds__(256)
void embed_kernel(const float* __restrict__ x,
                  const float* __restrict__ emb_w, const float* __restrict__ emb_b,
                  const float* __restrict__ proj_w, const float* __restrict__ proj_b)
{
    int gwarp = (blockIdx.x * blockDim.x + threadIdx.x) >> 5;
    int lane  = threadIdx.x & 31;
    if (gwarp >= BLR) return;
    int rid = gwarp;
    int d = rid % DD;
    int l = rid % LL;

    float xr[PP]; float n2 = 0.f;
#pragma unroll
    for (int p = 0; p < PP; p++) { xr[p] = x[(size_t)rid*PP + p]; n2 += xr[p]*xr[p]; }
    float nr = fmaxf(sqrtf(n2), 1e-12f);
    float xn[PP];
#pragma unroll
    for (int p = 0; p < PP; p++) xn[p] = xr[p] / nr;

    const float* pn = g_pn + (size_t)d * KK * PP;
    float s = 0.f;
#pragma unroll
    for (int p = 0; p < PP; p++) s += xn[p] * pn[lane*PP + p];

    float bv = s; int bi = lane;
#pragma unroll
    for (int o = 16; o > 0; o >>= 1) {
        float ov = __shfl_xor_sync(0xffffffffu, bv, o);
        int   oi = __shfl_xor_sync(0xffffffffu, bi, o);
        if (ov > bv || (ov == bv && oi < bi)) { bv = ov; bi = oi; }
    }
    float sel[PP];
#pragma unroll
    for (int p = 0; p < PP; p++) sel[p] = pn[bi*PP + p];

#pragma unroll
    for (int j = 0; j < 4; j++) {
        int e = lane + (j << 5);
        float v = emb_b[e] + proj_b[e] + g_pos[l*EE + e];
#pragma unroll
        for (int p = 0; p < PP; p++)
            v += xr[p] * emb_w[e*PP + p] + sel[p] * proj_w[e*PP + p];
        g_seq[(size_t)rid*EE + e] = v;
    }
}

// ========== tf32 mma GEMM: C[M,N] = A[M,Kd] @ W[N,Kd]^T + bias ===============
template <int NT, int ACT, int FLN>
__global__ __launch_bounds__(256, 2)
void mma_gemm(const float* __restrict__ A, const float* __restrict__ W,
              const float* __restrict__ bias, float* __restrict__ C,
              const float* __restrict__ gam, const float* __restrict__ bet,
              int N, int Kd)
{
    constexpr int SA = 132;
    constexpr int SB = NT + 4;
    constexpr int NF = NT/8;
    __shared__ uint32_t As[32*SA];
    __shared__ uint32_t Bs[32*SB];
    int tid = threadIdx.x;
    int w = tid >> 5, lane = tid & 31;
    int m0 = blockIdx.y << 7, n0 = blockIdx.x * NT;
    int mw = w*16;
    int lq = lane >> 2;
    int lr = lane & 3;

    float acc[NF][4];
#pragma unroll
    for (int j = 0; j < NF; j++)
#pragma unroll
        for (int t = 0; t < 4; t++) acc[j][t] = 0.f;

    for (int k0 = 0; k0 < Kd; k0 += 32) {
#pragma unroll
        for (int i = 0; i < 4; i++) {
            int idx = tid + (i << 8);
            int m = idx >> 3, g = idx & 7;
            float4 v = *(const float4*)(A + (size_t)(m0 + m) * Kd + k0 + g*4);
            As[(g*4+0)*SA + m] = tf32c(v.x);
            As[(g*4+1)*SA + m] = tf32c(v.y);
            As[(g*4+2)*SA + m] = tf32c(v.z);
            As[(g*4+3)*SA + m] = tf32c(v.w);
        }
#pragma unroll
        for (int i = 0; i < NT*8/256; i++) {
            int idx = tid + (i << 8);
            int n = idx >> 3, g = idx & 7;
            float4 v = *(const float4*)(W + (size_t)(n0 + n) * Kd + k0 + g*4);
            Bs[(g*4+0)*SB + n] = tf32c(v.x);
            Bs[(g*4+1)*SB + n] = tf32c(v.y);
            Bs[(g*4+2)*SB + n] = tf32c(v.z);
            Bs[(g*4+3)*SB + n] = tf32c(v.w);
        }
        __syncthreads();
#pragma unroll
        for (int k8 = 0; k8 < 4; k8++) {
            int kk = k8*8;
            uint32_t a0 = As[(kk + lr)*SA + mw + lq];
            uint32_t a1 = As[(kk + lr)*SA + mw + 8 + lq];
            uint32_t a2 = As[(kk + 4 + lr)*SA + mw + lq];
            uint32_t a3 = As[(kk + 4 + lr)*SA + mw + 8 + lq];
#pragma unroll
            for (int j = 0; j < NF; j++) {
                uint32_t b0 = Bs[(kk + lr)*SB + j*8 + lq];
                uint32_t b1 = Bs[(kk + 4 + lr)*SB + j*8 + lq];
                mma8(acc[j], a0, a1, a2, a3, b0, b1);
            }
        }
        __syncthreads();
    }

    int r0 = m0 + mw + lq;
    int cb = 2*lr;

    if (!FLN) {
#pragma unroll
        for (int j = 0; j < NF; j++) {
            int n = n0 + j*8 + cb;
            float2 bv = *(const float2*)(bias + n);
            float x0 = acc[j][0] + bv.x, x1 = acc[j][1] + bv.y;
            float x2 = acc[j][2] + bv.x, x3 = acc[j][3] + bv.y;
            if (ACT) {
                x0 = (x0 > 0.f) ? x0 : expm1f(x0);
                x1 = (x1 > 0.f) ? x1 : expm1f(x1);
                x2 = (x2 > 0.f) ? x2 : expm1f(x2);
                x3 = (x3 > 0.f) ? x3 : expm1f(x3);
            }
            float2 o0; o0.x = x0; o0.y = x1;
            float2 o1; o1.x = x2; o1.y = x3;
            *(float2*)(C + (size_t)r0 * N + n)     = o0;
            *(float2*)(C + (size_t)(r0+8) * N + n) = o1;
        }
    } else {
        float s0 = 0.f, s1 = 0.f;
#pragma unroll
        for (int j = 0; j < NF; j++) {
            int n = j*8 + cb;
            float2 bv = *(const float2*)(bias + n);
            float2 e0 = *(const float2*)(C + (size_t)r0*128 + n);
            float2 e1 = *(const float2*)(C + (size_t)(r0+8)*128 + n);
            acc[j][0] += bv.x + e0.x;  acc[j][1] += bv.y + e0.y;
            acc[j][2] += bv.x + e1.x;  acc[j][3] += bv.y + e1.y;
            s0 += acc[j][0] + acc[j][1];
            s1 += acc[j][2] + acc[j][3];
        }
        s0 += __shfl_xor_sync(0xffffffffu, s0, 1);
        s0 += __shfl_xor_sync(0xffffffffu, s0, 2);
        s1 += __shfl_xor_sync(0xffffffffu, s1, 1);
        s1 += __shfl_xor_sync(0xffffffffu, s1, 2);
        float mean0 = s0 * (1.0f/128.0f);
        float mean1 = s1 * (1.0f/128.0f);
        float q0 = 0.f, q1 = 0.f;
#pragma unroll
        for (int j = 0; j < NF; j++) {
            acc[j][0] -= mean0; acc[j][1] -= mean0;
            acc[j][2] -= mean1; acc[j][3] -= mean1;
            q0 += acc[j][0]*acc[j][0] + acc[j][1]*acc[j][1];
            q1 += acc[j][2]*acc[j][2] + acc[j][3]*acc[j][3];
        }
        q0 += __shfl_xor_sync(0xffffffffu, q0, 1);
        q0 += __shfl_xor_sync(0xffffffffu, q0, 2);
        q1 += __shfl_xor_sync(0xffffffffu, q1, 1);
        q1 += __shfl_xor_sync(0xffffffffu, q1, 2);
        float rstd0 = rsqrtf(q0 * (1.0f/128.0f) + 1e-5f);
        float rstd1 = rsqrtf(q1 * (1.0f/128.0f) + 1e-5f);
#pragma unroll
        for (int j = 0; j < NF; j++) {
            int n = j*8 + cb;
            float2 gv = *(const float2*)(gam + n);
            float2 bt = *(const float2*)(bet + n);
            float2 o0, o1;
            o0.x = acc[j][0]*rstd0*gv.x + bt.x;
            o0.y = acc[j][1]*rstd0*gv.y + bt.y;
            o1.x = acc[j][2]*rstd1*gv.x + bt.x;
            o1.y = acc[j][3]*rstd1*gv.y + bt.y;
            *(float2*)(C + (size_t)r0*128 + n)     = o0;
            *(float2*)(C + (size_t)(r0+8)*128 + n) = o1;
        }
    }
}

// ========== attention on mma.sync: block=(qtile,h,b), 256 thr, 8 warps ========
// Per 64-key chunk: S = Q·K^T (tf32 mma, scale*log2e folded into Q), ex2 on the
// C fragment, then C→A fragment conversion via 8 intra-quad shuffles, P·V mma.
// Max-free softmax (logits O(1)); deterministic chunk order.
#define ACH 64
#define NCHUNK (LL/ACH)   // 12
__global__ __launch_bounds__(256)
void attn_mma_kernel(const float* __restrict__ qkv, float* __restrict__ ctx)
{
    __shared__ uint32_t Ks[ACH*20];   // [key][dim] stride 20 — B-frag conflict-free
    __shared__ uint32_t Vs[ACH*24];   // [key][dim] stride 24 — B-frag conflict-free
    int qt = blockIdx.x, h = blockIdx.y, b = blockIdx.z;
    int tid = threadIdx.x;
    int w = tid >> 5, lane = tid & 31;
    int lq = lane >> 2, lr = lane & 3;
    const float SC = 0.25f * 1.4426950408889634f;
    const float* base = qkv + (size_t)b * LL * (3*EE) + h*HD;

    // Q A-fragments, loaded once (2 ksteps x 4 regs), scale folded
    uint32_t qa[2][4];
    {
        const float* q0 = base + (size_t)(qt*128 + w*16 + lq) * (3*EE);
        const float* q1 = q0 + (size_t)8 * (3*EE);
#pragma unroll
        for (int ks = 0; ks < 2; ks++) {
            qa[ks][0] = tf32c(q0[ks*8 + lr]     * SC);
            qa[ks][1] = tf32c(q1[ks*8 + lr]     * SC);
            qa[ks][2] = tf32c(q0[ks*8 + 4 + lr] * SC);
            qa[ks][3] = tf32c(q1[ks*8 + 4 + lr] * SC);
        }
    }

    float acc[2][4];    // ctx accumulators: 2 dim-frags (n=0..7, 8..15)
#pragma unroll
    for (int nf = 0; nf < 2; nf++)
#pragma unroll
        for (int t = 0; t < 4; t++) acc[nf][t] = 0.f;
    float s0 = 0.f, s1 = 0.f;   // exp row-sums (rows lq, lq+8)

    for (int c = 0; c < NCHUNK; c++) {
        __syncthreads();
        {   // load K/V chunk (64 keys x 16 dims), convert to tf32
            int m = tid >> 2, part = (tid & 3) << 2;
            const float* kp = base + (size_t)(c*ACH + m) * (3*EE) + EE + part;
            float4 kv = *(const float4*)kp;
            float4 vv = *(const float4*)(kp + EE);
            Ks[m*20 + part + 0] = tf32c(kv.x);
            Ks[m*20 + part + 1] = tf32c(kv.y);
            Ks[m*20 + part + 2] = tf32c(kv.z);
            Ks[m*20 + part + 3] = tf32c(kv.w);
            Vs[m*24 + part + 0] = tf32c(vv.x);
            Vs[m*24 + part + 1] = tf32c(vv.y);
            Vs[m*24 + part + 2] = tf32c(vv.z);
            Vs[m*24 + part + 3] = tf32c(vv.w);
        }
        __syncthreads();

#pragma unroll
        for (int j = 0; j < 8; j++) {
            // S fragment for keys [c*64 + j*8, +8)
            float sf[4] = {0.f, 0.f, 0.f, 0.f};
#pragma unroll
            for (int ks = 0; ks < 2; ks++) {
                uint32_t b0 = Ks[(j*8 + lq)*20 + ks*8 + lr];
                uint32_t b1 = Ks[(j*8 + lq)*20 + ks*8 + 4 + lr];
                mma8(sf, qa[ks][0], qa[ks][1], qa[ks][2], qa[ks][3], b0, b1);
            }
            float e0 = ex2f(sf[0]), e1 = ex2f(sf[1]);
            float e2 = ex2f(sf[2]), e3 = ex2f(sf[3]);
            s0 += e0 + e1;  s1 += e2 + e3;
            uint32_t f0 = tf32c(e0), f1 = tf32c(e1);
            uint32_t f2 = tf32c(e2), f3 = tf32c(e3);
            // C-frag (cols 2lr,2lr+1) -> A-frag (k = lr, lr+4) via quad shuffles
            int src0 = (lane & 28) | (lr >> 1);
            int src2 = src0 + 2;
            uint32_t t00 = __shfl_sync(0xffffffffu, f0, src0);
            uint32_t t01 = __shfl_sync(0xffffffffu, f1, src0);
            uint32_t t02 = __shfl_sync(0xffffffffu, f2, src0);
            uint32_t t03 = __shfl_sync(0xffffffffu, f3, src0);
            uint32_t t20 = __shfl_sync(0xffffffffu, f0, src2);
            uint32_t t21 = __shfl_sync(0xffffffffu, f1, src2);
            uint32_t t22 = __shfl_sync(0xffffffffu, f2, src2);
            uint32_t t23 = __shfl_sync(0xffffffffu, f3, src2);
            bool odd = (lr & 1);
            uint32_t a0 = odd ? t01 : t00;   // row lq,   k=lr
            uint32_t a1 = odd ? t03 : t02;   // row lq+8, k=lr
            uint32_t a2 = odd ? t21 : t20;   // row lq,   k=lr+4
            uint32_t a3 = odd ? t23 : t22;   // row lq+8, k=lr+4
            // P·V for this 8-key step
#pragma unroll
            for (int nf = 0; nf < 2; nf++) {
                uint32_t b0 = Vs[(j*8 + lr)*24 + nf*8 + lq];
                uint32_t b1 = Vs[(j*8 + 4 + lr)*24 + nf*8 + lq];
                mma8(acc[nf], a0, a1, a2, a3, b0, b1);
            }
        }
    }

    // row-sum reduce over the quad (lanes sharing lq)
    s0 += __shfl_xor_sync(0xffffffffu, s0, 1);
    s0 += __shfl_xor_sync(0xffffffffu, s0, 2);
    s1 += __shfl_xor_sync(0xffffffffu, s1, 1);
    s1 += __shfl_xor_sync(0xffffffffu, s1, 2);
    float inv0 = 1.0f / s0, inv1 = 1.0f / s1;

    float* o0 = ctx + (size_t)(b*LL + qt*128 + w*16 + lq) * EE + h*HD;
    float* o1 = o0 + (size_t)8 * EE;
#pragma unroll
    for (int nf = 0; nf < 2; nf++) {
        float2 r0; r0.x = acc[nf][0] * inv0;  r0.y = acc[nf][1] * inv0;
        float2 r1; r1.x = acc[nf][2] * inv1;  r1.y = acc[nf][3] * inv1;
        *(float2*)(o0 + nf*8 + 2*lr) = r0;
        *(float2*)(o1 + nf*8 + 2*lr) = r1;
    }
}

// ---------------- final projection (packed ffma2) ----------------
__global__ __launch_bounds__(256)
void final_partial(const float* __restrict__ seq, const float* __restrict__ ow,
                   float* __restrict__ part)
{
    extern __shared__ float smf[];
    float* Ws  = smf;
    float* As2 = smf + 128*136;
    int l = blockIdx.x, tid = threadIdx.x;
    for (int idx = tid; idx < OUTN*EE; idx += 256) {
        int o = idx >> 7, e = idx & 127;
        Ws[e*136 + o] = ow[(size_t)o * (LL*EE) + l*EE + e];
    }
    for (int idx = tid; idx < BB*EE; idx += 256) {
        int b = idx >> 7, e = idx & 127;
        As2[e*34 + b] = seq[(size_t)b * (LL*EE) + l*EE + e];
    }
    __syncthreads();
    int tx = tid & 15, ty = tid >> 4;
    u64 acc[2][4];
#pragma unroll
    for (int i = 0; i < 2; i++)
#pragma unroll
        for (int j = 0; j < 4; j++) acc[i][j] = pack2(0.f, 0.f);
#pragma unroll 4
    for (int e = 0; e < EE; e++) {
        u64 a0 = pack2(As2[e*34 + ty*2],     As2[e*34 + ty*2]);
        u64 a1 = pack2(As2[e*34 + ty*2 + 1], As2[e*34 + ty*2 + 1]);
        ulonglong2 w01 = *(const ulonglong2*)(Ws + e*136 + tx*8);
        ulonglong2 w23 = *(const ulonglong2*)(Ws + e*136 + tx*8 + 4);
        acc[0][0]=ffma2(a0,w01.x,acc[0][0]); acc[0][1]=ffma2(a0,w01.y,acc[0][1]);
        acc[0][2]=ffma2(a0,w23.x,acc[0][2]); acc[0][3]=ffma2(a0,w23.y,acc[0][3]);
        acc[1][0]=ffma2(a1,w01.x,acc[1][0]); acc[1][1]=ffma2(a1,w01.y,acc[1][1]);
        acc[1][2]=ffma2(a1,w23.x,acc[1][2]); acc[1][3]=ffma2(a1,w23.y,acc[1][3]);
    }
#pragma unroll
    for (int i = 0; i < 2; i++) {
        int b = ty*2 + i;
        float* dst = part + (size_t)l * (BB*OUTN) + b*OUTN + tx*8;
#pragma unroll
        for (int j = 0; j < 4; j++) {
            float lo, hi; unpack2(acc[i][j], lo, hi);
            float2 o; o.x = lo; o.y = hi;
            *(float2*)(dst + j*2) = o;
        }
    }
}

// ---------------- final reduce: one warp per output ----------------
__global__ __launch_bounds__(256)
void final_reduce2(const float* __restrict__ part,
                   const float* __restrict__ out_b, float* __restrict__ out)
{
    int gw = (blockIdx.x * 256 + threadIdx.x) >> 5;
    int lane = threadIdx.x & 31;
    float s = 0.f;
#pragma unroll
    for (int t = 0; t < 24; t++)
        s += part[(size_t)(lane + t*32) * (BB*OUTN) + gw];
#pragma unroll
    for (int o = 16; o > 0; o >>= 1) s += __shfl_xor_sync(0xffffffffu, s, o);
    if (lane == 0) out[gw] = s + out_b[gw & 127];
}

// ---------------- host launcher ----------------
extern "C" void kernel_launch(void* const* d_in, const int* in_sizes, int n_in,
                              void* d_out, int out_size)
{
    const float* x          = (const float*)d_in[0];
    const float* prototypes = (const float*)d_in[1];
    const float* emb_w      = (const float*)d_in[2];
    const float* emb_b      = (const float*)d_in[3];
    const float* proj_w     = (const float*)d_in[4];
    const float* proj_b     = (const float*)d_in[5];
    const float* in_proj_w  = (const float*)d_in[6];
    const float* in_proj_b  = (const float*)d_in[7];
    const float* out_proj_w = (const float*)d_in[8];
    const float* out_proj_b = (const float*)d_in[9];
    const float* ln1_s      = (const float*)d_in[10];
    const float* ln1_b      = (const float*)d_in[11];
    const float* ffn_w1     = (const float*)d_in[12];
    const float* ffn_b1     = (const float*)d_in[13];
    const float* ffn_w2     = (const float*)d_in[14];
    const float* ffn_b2     = (const float*)d_in[15];
    const float* ln2_s      = (const float*)d_in[16];
    const float* ln2_b      = (const float*)d_in[17];
    const float* out_w      = (const float*)d_in[18];
    const float* out_b      = (const float*)d_in[19];
    float* out = (float*)d_out;

    float *seq, *qkv, *ctx, *hid, *part;
    cudaGetSymbolAddress((void**)&seq,   g_seq);
    cudaGetSymbolAddress((void**)&qkv,   g_qkv);
    cudaGetSymbolAddress((void**)&ctx,   g_ctx);
    cudaGetSymbolAddress((void**)&hid,   g_hid);
    cudaGetSymbolAddress((void**)&part,  g_part);

    const int FIN_SMEM  = (128*136 + 128*34) * 4;        // 87040
    cudaFuncSetAttribute(final_partial, cudaFuncAttributeMaxDynamicSharedMemorySize, FIN_SMEM);

    proto_norm_kernel<<<12, 256>>>(prototypes);
    pos_kernel<<<(LL*EE)/256, 256>>>();
    embed_kernel<<<BLR/8, 256>>>(x, emb_w, emb_b, proj_w, proj_b);

    for (int l = 0; l < 2; l++) {
        // qkv = seq @ in_proj_w[l]^T + b   (M=24576, N=384, K=128)
        mma_gemm<128,0,0><<<dim3(3, BLR/128), 256>>>(
            seq, in_proj_w + (size_t)l*3*EE*EE, in_proj_b + l*3*EE, qkv,
            nullptr, nullptr, 3*EE, EE);
        attn_mma_kernel<<<dim3(LL/128, HH, BB), 256>>>(qkv, ctx);
        // seq = LN1(seq + ctx @ out_proj_w[l]^T + b)   (fused)
        mma_gemm<128,0,1><<<dim3(1, BLR/128), 256>>>(
            ctx, out_proj_w + (size_t)l*EE*EE, out_proj_b + l*EE, seq,
            ln1_s + l*EE, ln1_b + l*EE, EE, EE);
        // hid = elu(seq @ w1^T + b1)   (N=64, K=128)
        mma_gemm<64,1,0><<<dim3(1, BLR/128), 256>>>(
            seq, ffn_w1 + (size_t)l*II*EE, ffn_b1 + l*II, hid,
            nullptr, nullptr, II, EE);
        // seq = LN2(seq + hid @ w2^T + b2)   (fused; K=64)
        mma_gemm<128,0,1><<<dim3(1, BLR/128), 256>>>(
            hid, ffn_w2 + (size_t)l*EE*II, ffn_b2 + l*EE, seq,
            ln2_s + l*EE, ln2_b + l*EE, EE, II);
    }

    final_partial<<<LL, 256, FIN_SMEM>>>(seq, out_w, part);
    final_reduce2<<<(BB*OUTN*32)/256, 256>>>(part, out_b, out);
}

// round 13
// speedup vs baseline: 5.0603x; 1.0821x over previous
#include <cuda_runtime.h>
#include <cstdint>
#include <math.h>

#define BB   32
#define PP   6
#define DD   96
#define EE   128
#define HH   8
#define HD   16
#define II   64
#define KK   32
#define LL   768
#define BLR  (BB*LL)      // 24576 rows
#define OUTN 128

typedef unsigned long long u64;
__device__ __forceinline__ u64 pack2(float lo, float hi){
    u64 r; asm("mov.b64 %0,{%1,%2};" : "=l"(r) : "f"(lo), "f"(hi)); return r;
}
__device__ __forceinline__ void unpack2(u64 v, float& lo, float& hi){
    asm("mov.b64 {%0,%1},%2;" : "=f"(lo), "=f"(hi) : "l"(v));
}
__device__ __forceinline__ u64 ffma2(u64 a, u64 b, u64 c){
    u64 d; asm("fma.rn.f32x2 %0,%1,%2,%3;" : "=l"(d) : "l"(a), "l"(b), "l"(c)); return d;
}
__device__ __forceinline__ float ex2f(float x){
    float r; asm("ex2.approx.f32 %0, %1;" : "=f"(r) : "f"(x)); return r;
}
__device__ __forceinline__ uint32_t tf32c(float x){
    uint32_t r; asm("cvt.rna.tf32.f32 %0, %1;" : "=r"(r) : "f"(x)); return r;
}
__device__ __forceinline__ void mma8(float* d, uint32_t a0, uint32_t a1,
                                     uint32_t a2, uint32_t a3,
                                     uint32_t b0, uint32_t b1){
    asm volatile("mma.sync.aligned.m16n8k8.row.col.f32.tf32.tf32.f32 "
        "{%0,%1,%2,%3},{%4,%5,%6,%7},{%8,%9},{%0,%1,%2,%3};"
        : "+f"(d[0]), "+f"(d[1]), "+f"(d[2]), "+f"(d[3])
        : "r"(a0), "r"(a1), "r"(a2), "r"(a3), "r"(b0), "r"(b1));
}

// ---------------- scratch ----------------
__device__ float g_seq  [BLR*EE];
__device__ float g_qkv  [BLR*3*EE];
__device__ float g_ctx  [BLR*EE];
__device__ float g_hid  [BLR*II];
__device__ float g_pn   [DD*KK*PP];
__device__ float g_pos  [LL*EE];
__device__ float g_part [LL*BB*OUTN];

// ---------------- prototype normalization ----------------
__global__ void proto_norm_kernel(const float* __restrict__ proto) {
    int i = blockIdx.x * 256 + threadIdx.x;
    if (i >= DD*KK) return;
    float v[PP]; float n2 = 0.f;
#pragma unroll
    for (int p = 0; p < PP; p++) { v[p] = proto[i*PP + p]; n2 += v[p]*v[p]; }
    float nr = fmaxf(sqrtf(n2), 1e-12f);
#pragma unroll
    for (int p = 0; p < PP; p++) g_pn[i*PP + p] = v[p] / nr;
}

// ---------------- positional encoding ----------------
__global__ void pos_kernel() {
    int i = blockIdx.x * 256 + threadIdx.x;
    int l = i >> 7, e = i & 127;
    int half = e >> 1;
    float freq = expf(-(float)(2*half) * (logf(10000.0f) / (float)EE));
    float ang = (float)l * freq;
    g_pos[i] = (e & 1) ? cosf(ang) : sinf(ang);
}

// ---------------- embedding ----------------
__global__ __launch_bounds__(256)
void embed_kernel(const float* __restrict__ x,
                  const float* __restrict__ emb_w, const float* __restrict__ emb_b,
                  const float* __restrict__ proj_w, const float* __restrict__ proj_b)
{
    int gwarp = (blockIdx.x * blockDim.x + threadIdx.x) >> 5;
    int lane  = threadIdx.x & 31;
    if (gwarp >= BLR) return;
    int rid = gwarp;
    int d = rid % DD;
    int l = rid % LL;

    float xr[PP]; float n2 = 0.f;
#pragma unroll
    for (int p = 0; p < PP; p++) { xr[p] = x[(size_t)rid*PP + p]; n2 += xr[p]*xr[p]; }
    float nr = fmaxf(sqrtf(n2), 1e-12f);
    float xn[PP];
#pragma unroll
    for (int p = 0; p < PP; p++) xn[p] = xr[p] / nr;

    const float* pn = g_pn + (size_t)d * KK * PP;
    float s = 0.f;
#pragma unroll
    for (int p = 0; p < PP; p++) s += xn[p] * pn[lane*PP + p];

    float bv = s; int bi = lane;
#pragma unroll
    for (int o = 16; o > 0; o >>= 1) {
        float ov = __shfl_xor_sync(0xffffffffu, bv, o);
        int   oi = __shfl_xor_sync(0xffffffffu, bi, o);
        if (ov > bv || (ov == bv && oi < bi)) { bv = ov; bi = oi; }
    }
    float sel[PP];
#pragma unroll
    for (int p = 0; p < PP; p++) sel[p] = pn[bi*PP + p];

#pragma unroll
    for (int j = 0; j < 4; j++) {
        int e = lane + (j << 5);
        float v = emb_b[e] + proj_b[e] + g_pos[l*EE + e];
#pragma unroll
        for (int p = 0; p < PP; p++)
            v += xr[p] * emb_w[e*PP + p] + sel[p] * proj_w[e*PP + p];
        g_seq[(size_t)rid*EE + e] = v;
    }
}

// ========== tf32 mma GEMM v3: C[M,N] = A[M,Kd] @ W[N,Kd]^T + bias ============
// 128 threads = 4 warps; each warp owns 32 rows (2 m16 frags). B is stored in
// smem pre-packed in fragment order (per-lane stride NFp = 4*odd words ->
// conflict-free LDS.128). ACT=1: ELU. FLN=1: fused residual+layernorm
// (requires NT==N==128; C is the residual stream, updated in place).
template <int NT, int ACT, int FLN>
__global__ __launch_bounds__(128)
void mma_gemm3(const float* __restrict__ A, const float* __restrict__ W,
               const float* __restrict__ bias, float* __restrict__ C,
               const float* __restrict__ gam, const float* __restrict__ bet,
               int N, int Kd)
{
    constexpr int NF  = NT/8;                 // 16 or 8
    constexpr int NFp = (NF == 16) ? 20 : 12; // 4*odd: conflict-free vec4 LDS
    constexpr int SA  = 132;
    __shared__ __align__(16) uint32_t As [32*SA];
    __shared__ __align__(16) uint32_t Bp0[4*32*NFp];
    __shared__ __align__(16) uint32_t Bp1[4*32*NFp];
    int tid = threadIdx.x;
    int w = tid >> 5, lane = tid & 31;
    int lq = lane >> 2, lr = lane & 3;
    int m0 = blockIdx.y << 7, n0 = blockIdx.x * NT;
    int mw = w << 5;

    float acc[2][NF][4];
#pragma unroll
    for (int f = 0; f < 2; f++)
#pragma unroll
        for (int j = 0; j < NF; j++)
#pragma unroll
            for (int t = 0; t < 4; t++) acc[f][j][t] = 0.f;

    for (int k0 = 0; k0 < Kd; k0 += 32) {
#pragma unroll
        for (int i = 0; i < 8; i++) {               // A: 128 rows x 32 k
            int idx = tid + (i << 7);
            int m = idx >> 3, g = idx & 7;
            float4 v = *(const float4*)(A + (size_t)(m0 + m) * Kd + k0 + g*4);
            As[(g*4+0)*SA + m] = tf32c(v.x);
            As[(g*4+1)*SA + m] = tf32c(v.y);
            As[(g*4+2)*SA + m] = tf32c(v.z);
            As[(g*4+3)*SA + m] = tf32c(v.w);
        }
#pragma unroll
        for (int i = 0; i < NT/16; i++) {           // B: NT rows x 32 k, packed
            int idx = tid + (i << 7);
            int n = idx >> 3, g = idx & 7;
            float4 v = *(const float4*)(W + (size_t)(n0 + n) * Kd + k0 + g*4);
            uint32_t* dst = ((g & 1) ? Bp1 : Bp0)
                          + (((g >> 1)*32) + ((n & 7) << 2))*NFp + (n >> 3);
            dst[0*NFp] = tf32c(v.x);
            dst[1*NFp] = tf32c(v.y);
            dst[2*NFp] = tf32c(v.z);
            dst[3*NFp] = tf32c(v.w);
        }
        __syncthreads();
#pragma unroll
        for (int k8 = 0; k8 < 4; k8++) {
            int kk = k8*8;
            uint32_t a0[4], a1[4];
            a0[0] = As[(kk + lr)*SA + mw + lq];
            a0[1] = As[(kk + lr)*SA + mw + 8 + lq];
            a0[2] = As[(kk + 4 + lr)*SA + mw + lq];
            a0[3] = As[(kk + 4 + lr)*SA + mw + 8 + lq];
            a1[0] = As[(kk + lr)*SA + mw + 16 + lq];
            a1[1] = As[(kk + lr)*SA + mw + 24 + lq];
            a1[2] = As[(kk + 4 + lr)*SA + mw + 16 + lq];
            a1[3] = As[(kk + 4 + lr)*SA + mw + 24 + lq];
            const uint32_t* bp0 = Bp0 + (k8*32 + lane)*NFp;
            const uint32_t* bp1 = Bp1 + (k8*32 + lane)*NFp;
#pragma unroll
            for (int jv = 0; jv < NF/4; jv++) {
                uint4 b0v = *(const uint4*)(bp0 + jv*4);
                uint4 b1v = *(const uint4*)(bp1 + jv*4);
                mma8(acc[0][jv*4+0], a0[0],a0[1],a0[2],a0[3], b0v.x, b1v.x);
                mma8(acc[1][jv*4+0], a1[0],a1[1],a1[2],a1[3], b0v.x, b1v.x);
                mma8(acc[0][jv*4+1], a0[0],a0[1],a0[2],a0[3], b0v.y, b1v.y);
                mma8(acc[1][jv*4+1], a1[0],a1[1],a1[2],a1[3], b0v.y, b1v.y);
                mma8(acc[0][jv*4+2], a0[0],a0[1],a0[2],a0[3], b0v.z, b1v.z);
                mma8(acc[1][jv*4+2], a1[0],a1[1],a1[2],a1[3], b0v.z, b1v.z);
                mma8(acc[0][jv*4+3], a0[0],a0[1],a0[2],a0[3], b0v.w, b1v.w);
                mma8(acc[1][jv*4+3], a1[0],a1[1],a1[2],a1[3], b0v.w, b1v.w);
            }
        }
        __syncthreads();
    }

#pragma unroll
    for (int f = 0; f < 2; f++) {
        int r0 = m0 + mw + f*16 + lq;
        if (!FLN) {
#pragma unroll
            for (int j = 0; j < NF; j++) {
                int n = n0 + j*8 + 2*lr;
                float2 bv = *(const float2*)(bias + n);
                float x0 = acc[f][j][0] + bv.x, x1 = acc[f][j][1] + bv.y;
                float x2 = acc[f][j][2] + bv.x, x3 = acc[f][j][3] + bv.y;
                if (ACT) {
                    x0 = (x0 > 0.f) ? x0 : expm1f(x0);
                    x1 = (x1 > 0.f) ? x1 : expm1f(x1);
                    x2 = (x2 > 0.f) ? x2 : expm1f(x2);
                    x3 = (x3 > 0.f) ? x3 : expm1f(x3);
                }
                float2 o0; o0.x = x0; o0.y = x1;
                float2 o1; o1.x = x2; o1.y = x3;
                *(float2*)(C + (size_t)r0 * N + n)     = o0;
                *(float2*)(C + (size_t)(r0+8) * N + n) = o1;
            }
        } else {
            float s0 = 0.f, s1 = 0.f;
#pragma unroll
            for (int j = 0; j < NF; j++) {
                int n = j*8 + 2*lr;
                float2 bv = *(const float2*)(bias + n);
                float2 e0 = *(const float2*)(C + (size_t)r0*128 + n);
                float2 e1 = *(const float2*)(C + (size_t)(r0+8)*128 + n);
                acc[f][j][0] += bv.x + e0.x;  acc[f][j][1] += bv.y + e0.y;
                acc[f][j][2] += bv.x + e1.x;  acc[f][j][3] += bv.y + e1.y;
                s0 += acc[f][j][0] + acc[f][j][1];
                s1 += acc[f][j][2] + acc[f][j][3];
            }
            s0 += __shfl_xor_sync(0xffffffffu, s0, 1);
            s0 += __shfl_xor_sync(0xffffffffu, s0, 2);
            s1 += __shfl_xor_sync(0xffffffffu, s1, 1);
            s1 += __shfl_xor_sync(0xffffffffu, s1, 2);
            float mean0 = s0 * (1.0f/128.0f);
            float mean1 = s1 * (1.0f/128.0f);
            float q0 = 0.f, q1 = 0.f;
#pragma unroll
            for (int j = 0; j < NF; j++) {
                acc[f][j][0] -= mean0; acc[f][j][1] -= mean0;
                acc[f][j][2] -= mean1; acc[f][j][3] -= mean1;
                q0 += acc[f][j][0]*acc[f][j][0] + acc[f][j][1]*acc[f][j][1];
                q1 += acc[f][j][2]*acc[f][j][2] + acc[f][j][3]*acc[f][j][3];
            }
            q0 += __shfl_xor_sync(0xffffffffu, q0, 1);
            q0 += __shfl_xor_sync(0xffffffffu, q0, 2);
            q1 += __shfl_xor_sync(0xffffffffu, q1, 1);
            q1 += __shfl_xor_sync(0xffffffffu, q1, 2);
            float rstd0 = rsqrtf(q0 * (1.0f/128.0f) + 1e-5f);
            float rstd1 = rsqrtf(q1 * (1.0f/128.0f) + 1e-5f);
#pragma unroll
            for (int j = 0; j < NF; j++) {
                int n = j*8 + 2*lr;
                float2 gv = *(const float2*)(gam + n);
                float2 bt = *(const float2*)(bet + n);
                float2 o0, o1;
                o0.x = acc[f][j][0]*rstd0*gv.x + bt.x;
                o0.y = acc[f][j][1]*rstd0*gv.y + bt.y;
                o1.x = acc[f][j][2]*rstd1*gv.x + bt.x;
                o1.y = acc[f][j][3]*rstd1*gv.y + bt.y;
                *(float2*)(C + (size_t)r0*128 + n)     = o0;
                *(float2*)(C + (size_t)(r0+8)*128 + n) = o1;
            }
        }
    }
}

// ========== attention on mma.sync: block=(qtile,h,b), 256 thr, 8 warps ========
#define ACH 64
#define NCHUNK (LL/ACH)   // 12
__global__ __launch_bounds__(256)
void attn_mma_kernel(const float* __restrict__ qkv, float* __restrict__ ctx)
{
    __shared__ uint32_t Ks[ACH*20];
    __shared__ uint32_t Vs[ACH*24];
    int qt = blockIdx.x, h = blockIdx.y, b = blockIdx.z;
    int tid = threadIdx.x;
    int w = tid >> 5, lane = tid & 31;
    int lq = lane >> 2, lr = lane & 3;
    const float SC = 0.25f * 1.4426950408889634f;
    const float* base = qkv + (size_t)b * LL * (3*EE) + h*HD;

    uint32_t qa[2][4];
    {
        const float* q0 = base + (size_t)(qt*128 + w*16 + lq) * (3*EE);
        const float* q1 = q0 + (size_t)8 * (3*EE);
#pragma unroll
        for (int ks = 0; ks < 2; ks++) {
            qa[ks][0] = tf32c(q0[ks*8 + lr]     * SC);
            qa[ks][1] = tf32c(q1[ks*8 + lr]     * SC);
            qa[ks][2] = tf32c(q0[ks*8 + 4 + lr] * SC);
            qa[ks][3] = tf32c(q1[ks*8 + 4 + lr] * SC);
        }
    }

    float acc[2][4];
#pragma unroll
    for (int nf = 0; nf < 2; nf++)
#pragma unroll
        for (int t = 0; t < 4; t++) acc[nf][t] = 0.f;
    float s0 = 0.f, s1 = 0.f;

    for (int c = 0; c < NCHUNK; c++) {
        __syncthreads();
        {
            int m = tid >> 2, part = (tid & 3) << 2;
            const float* kp = base + (size_t)(c*ACH + m) * (3*EE) + EE + part;
            float4 kv = *(const float4*)kp;
            float4 vv = *(const float4*)(kp + EE);
            Ks[m*20 + part + 0] = tf32c(kv.x);
            Ks[m*20 + part + 1] = tf32c(kv.y);
            Ks[m*20 + part + 2] = tf32c(kv.z);
            Ks[m*20 + part + 3] = tf32c(kv.w);
            Vs[m*24 + part + 0] = tf32c(vv.x);
            Vs[m*24 + part + 1] = tf32c(vv.y);
            Vs[m*24 + part + 2] = tf32c(vv.z);
            Vs[m*24 + part + 3] = tf32c(vv.w);
        }
        __syncthreads();

#pragma unroll
        for (int j = 0; j < 8; j++) {
            float sf[4] = {0.f, 0.f, 0.f, 0.f};
#pragma unroll
            for (int ks = 0; ks < 2; ks++) {
                uint32_t b0 = Ks[(j*8 + lq)*20 + ks*8 + lr];
                uint32_t b1 = Ks[(j*8 + lq)*20 + ks*8 + 4 + lr];
                mma8(sf, qa[ks][0], qa[ks][1], qa[ks][2], qa[ks][3], b0, b1);
            }
            float e0 = ex2f(sf[0]), e1 = ex2f(sf[1]);
            float e2 = ex2f(sf[2]), e3 = ex2f(sf[3]);
            s0 += e0 + e1;  s1 += e2 + e3;
            uint32_t f0 = tf32c(e0), f1 = tf32c(e1);
            uint32_t f2 = tf32c(e2), f3 = tf32c(e3);
            int src0 = (lane & 28) | (lr >> 1);
            int src2 = src0 + 2;
            uint32_t t00 = __shfl_sync(0xffffffffu, f0, src0);
            uint32_t t01 = __shfl_sync(0xffffffffu, f1, src0);
            uint32_t t02 = __shfl_sync(0xffffffffu, f2, src0);
            uint32_t t03 = __shfl_sync(0xffffffffu, f3, src0);
            uint32_t t20 = __shfl_sync(0xffffffffu, f0, src2);
            uint32_t t21 = __shfl_sync(0xffffffffu, f1, src2);
            uint32_t t22 = __shfl_sync(0xffffffffu, f2, src2);
            uint32_t t23 = __shfl_sync(0xffffffffu, f3, src2);
            bool odd = (lr & 1);
            uint32_t a0 = odd ? t01 : t00;
            uint32_t a1 = odd ? t03 : t02;
            uint32_t a2 = odd ? t21 : t20;
            uint32_t a3 = odd ? t23 : t22;
#pragma unroll
            for (int nf = 0; nf < 2; nf++) {
                uint32_t b0 = Vs[(j*8 + lr)*24 + nf*8 + lq];
                uint32_t b1 = Vs[(j*8 + 4 + lr)*24 + nf*8 + lq];
                mma8(acc[nf], a0, a1, a2, a3, b0, b1);
            }
        }
    }

    s0 += __shfl_xor_sync(0xffffffffu, s0, 1);
    s0 += __shfl_xor_sync(0xffffffffu, s0, 2);
    s1 += __shfl_xor_sync(0xffffffffu, s1, 1);
    s1 += __shfl_xor_sync(0xffffffffu, s1, 2);
    float inv0 = 1.0f / s0, inv1 = 1.0f / s1;

    float* o0 = ctx + (size_t)(b*LL + qt*128 + w*16 + lq) * EE + h*HD;
    float* o1 = o0 + (size_t)8 * EE;
#pragma unroll
    for (int nf = 0; nf < 2; nf++) {
        float2 r0; r0.x = acc[nf][0] * inv0;  r0.y = acc[nf][1] * inv0;
        float2 r1; r1.x = acc[nf][2] * inv1;  r1.y = acc[nf][3] * inv1;
        *(float2*)(o0 + nf*8 + 2*lr) = r0;
        *(float2*)(o1 + nf*8 + 2*lr) = r1;
    }
}

// ========== final projection on mma: block per l, 128 thr, 4 warps ===========
// part[l] = seq[:, l*128:(l+1)*128] @ out_w[:, l*128:(l+1)*128]^T  (32x128x128)
__global__ __launch_bounds__(128)
void final_mma(const float* __restrict__ seq, const float* __restrict__ ow,
               float* __restrict__ part)
{
    constexpr int NFp = 20;
    constexpr int SAE = 36;
    __shared__ __align__(16) uint32_t Ae [128*SAE];
    __shared__ __align__(16) uint32_t Bp0[4*32*NFp];
    __shared__ __align__(16) uint32_t Bp1[4*32*NFp];
    int l = blockIdx.x, tid = threadIdx.x;
    int w = tid >> 5, lane = tid & 31;
    int lq = lane >> 2, lr = lane & 3;

    // A: 32 b-rows x 128 e, k-major
#pragma unroll
    for (int i = 0; i < 8; i++) {
        int idx = tid + (i << 7);           // 0..1023
        int b = idx >> 5, g = idx & 31;
        float4 v = *(const float4*)(seq + (size_t)b*(LL*EE) + l*EE + g*4);
        Ae[(g*4+0)*SAE + b] = tf32c(v.x);
        Ae[(g*4+1)*SAE + b] = tf32c(v.y);
        Ae[(g*4+2)*SAE + b] = tf32c(v.z);
        Ae[(g*4+3)*SAE + b] = tf32c(v.w);
    }

    float acc[2][4][4];
#pragma unroll
    for (int f = 0; f < 2; f++)
#pragma unroll
        for (int j = 0; j < 4; j++)
#pragma unroll
            for (int t = 0; t < 4; t++) acc[f][j][t] = 0.f;

    for (int k0 = 0; k0 < 128; k0 += 32) {
#pragma unroll
        for (int i = 0; i < 8; i++) {       // B: 128 o x 32 e, packed
            int idx = tid + (i << 7);
            int n = idx >> 3, g = idx & 7;
            float4 v = *(const float4*)(ow + (size_t)n*(LL*EE) + l*EE + k0 + g*4);
            uint32_t* dst = ((g & 1) ? Bp1 : Bp0)
                          + (((g >> 1)*32) + ((n & 7) << 2))*NFp + (n >> 3);
            dst[0*NFp] = tf32c(v.x);
            dst[1*NFp] = tf32c(v.y);
            dst[2*NFp] = tf32c(v.z);
            dst[3*NFp] = tf32c(v.w);
        }
        __syncthreads();
#pragma unroll
        for (int k8 = 0; k8 < 4; k8++) {
            int kk = k0 + k8*8;
            uint32_t a0[4], a1[4];
            a0[0] = Ae[(kk + lr)*SAE + lq];
            a0[1] = Ae[(kk + lr)*SAE + 8 + lq];
            a0[2] = Ae[(kk + 4 + lr)*SAE + lq];
            a0[3] = Ae[(kk + 4 + lr)*SAE + 8 + lq];
            a1[0] = Ae[(kk + lr)*SAE + 16 + lq];
            a1[1] = Ae[(kk + lr)*SAE + 24 + lq];
            a1[2] = Ae[(kk + 4 + lr)*SAE + 16 + lq];
            a1[3] = Ae[(kk + 4 + lr)*SAE + 24 + lq];
            const uint32_t* bp0 = Bp0 + (k8*32 + lane)*NFp + (w << 2);
            const uint32_t* bp1 = Bp1 + (k8*32 + lane)*NFp + (w << 2);
            uint4 b0v = *(const uint4*)bp0;
            uint4 b1v = *(const uint4*)bp1;
            mma8(acc[0][0], a0[0],a0[1],a0[2],a0[3], b0v.x, b1v.x);
            mma8(acc[1][0], a1[0],a1[1],a1[2],a1[3], b0v.x, b1v.x);
            mma8(acc[0][1], a0[0],a0[1],a0[2],a0[3], b0v.y, b1v.y);
            mma8(acc[1][1], a1[0],a1[1],a1[2],a1[3], b0v.y, b1v.y);
            mma8(acc[0][2], a0[0],a0[1],a0[2],a0[3], b0v.z, b1v.z);
            mma8(acc[1][2], a1[0],a1[1],a1[2],a1[3], b0v.z, b1v.z);
            mma8(acc[0][3], a0[0],a0[1],a0[2],a0[3], b0v.w, b1v.w);
            mma8(acc[1][3], a1[0],a1[1],a1[2],a1[3], b0v.w, b1v.w);
        }
        __syncthreads();
    }

    float* dst = part + (size_t)l * (BB*OUTN);
#pragma unroll
    for (int f = 0; f < 2; f++) {
        int br = f*16 + lq;
#pragma unroll
        for (int j = 0; j < 4; j++) {
            int o = (w << 5) + j*8 + 2*lr;
            float2 v0; v0.x = acc[f][j][0]; v0.y = acc[f][j][1];
            float2 v1; v1.x = acc[f][j][2]; v1.y = acc[f][j][3];
            *(float2*)(dst + br*OUTN + o)     = v0;
            *(float2*)(dst + (br+8)*OUTN + o) = v1;
        }
    }
}

// ---------------- final reduce: one warp per output ----------------
__global__ __launch_bounds__(256)
void final_reduce2(const float* __restrict__ part,
                   const float* __restrict__ out_b, float* __restrict__ out)
{
    int gw = (blockIdx.x * 256 + threadIdx.x) >> 5;
    int lane = threadIdx.x & 31;
    float s = 0.f;
#pragma unroll
    for (int t = 0; t < 24; t++)
        s += part[(size_t)(lane + t*32) * (BB*OUTN) + gw];
#pragma unroll
    for (int o = 16; o > 0; o >>= 1) s += __shfl_xor_sync(0xffffffffu, s, o);
    if (lane == 0) out[gw] = s + out_b[gw & 127];
}

// ---------------- host launcher ----------------
extern "C" void kernel_launch(void* const* d_in, const int* in_sizes, int n_in,
                              void* d_out, int out_size)
{
    const float* x          = (const float*)d_in[0];
    const float* prototypes = (const float*)d_in[1];
    const float* emb_w      = (const float*)d_in[2];
    const float* emb_b      = (const float*)d_in[3];
    const float* proj_w     = (const float*)d_in[4];
    const float* proj_b     = (const float*)d_in[5];
    const float* in_proj_w  = (const float*)d_in[6];
    const float* in_proj_b  = (const float*)d_in[7];
    const float* out_proj_w = (const float*)d_in[8];
    const float* out_proj_b = (const float*)d_in[9];
    const float* ln1_s      = (const float*)d_in[10];
    const float* ln1_b      = (const float*)d_in[11];
    const float* ffn_w1     = (const float*)d_in[12];
    const float* ffn_b1     = (const float*)d_in[13];
    const float* ffn_w2     = (const float*)d_in[14];
    const float* ffn_b2     = (const float*)d_in[15];
    const float* ln2_s      = (const float*)d_in[16];
    const float* ln2_b      = (const float*)d_in[17];
    const float* out_w      = (const float*)d_in[18];
    const float* out_b      = (const float*)d_in[19];
    float* out = (float*)d_out;

    float *seq, *qkv, *ctx, *hid, *part;
    cudaGetSymbolAddress((void**)&seq,   g_seq);
    cudaGetSymbolAddress((void**)&qkv,   g_qkv);
    cudaGetSymbolAddress((void**)&ctx,   g_ctx);
    cudaGetSymbolAddress((void**)&hid,   g_hid);
    cudaGetSymbolAddress((void**)&part,  g_part);

    proto_norm_kernel<<<12, 256>>>(prototypes);
    pos_kernel<<<(LL*EE)/256, 256>>>();
    embed_kernel<<<BLR/8, 256>>>(x, emb_w, emb_b, proj_w, proj_b);

    for (int l = 0; l < 2; l++) {
        // qkv = seq @ in_proj_w[l]^T + b   (M=24576, N=384, K=128)
        mma_gemm3<128,0,0><<<dim3(3, BLR/128), 128>>>(
            seq, in_proj_w + (size_t)l*3*EE*EE, in_proj_b + l*3*EE, qkv,
            nullptr, nullptr, 3*EE, EE);
        attn_mma_kernel<<<dim3(LL/128, HH, BB), 256>>>(qkv, ctx);
        // seq = LN1(seq + ctx @ out_proj_w[l]^T + b)   (fused)
        mma_gemm3<128,0,1><<<dim3(1, BLR/128), 128>>>(
            ctx, out_proj_w + (size_t)l*EE*EE, out_proj_b + l*EE, seq,
            ln1_s + l*EE, ln1_b + l*EE, EE, EE);
        // hid = elu(seq @ w1^T + b1)   (N=64, K=128)
        mma_gemm3<64,1,0><<<dim3(1, BLR/128), 128>>>(
            seq, ffn_w1 + (size_t)l*II*EE, ffn_b1 + l*II, hid,
            nullptr, nullptr, II, EE);
        // seq = LN2(seq + hid @ w2^T + b2)   (fused; K=64)
        mma_gemm3<128,0,1><<<dim3(1, BLR/128), 128>>>(
            hid, ffn_w2 + (size_t)l*EE*II, ffn_b2 + l*EE, seq,
            ln2_s + l*EE, ln2_b + l*EE, EE, II);
    }

    final_mma<<<LL, 128>>>(seq, out_w, part);
    final_reduce2<<<(BB*OUTN*32)/256, 256>>>(part, out_b, out);
}